// round 14
// baseline (speedup 1.0000x reference)
#include <cuda_runtime.h>
#include <cuda_fp16.h>
#include <math.h>
#include <stdint.h>

// ---------------- problem constants ----------------
#define D_    768
#define H_    12
#define HD_   64
#define FF_   3072
#define SEQ_  197
#define B_    32
#define NTOK  (B_ * SEQ_)     // 6304
#define MP_   6400            // padded token rows (50 * 128)
#define L_    12
#define E_    512
#define NP_   196
#define IMG_  224
#define P_    16

// ---------------- device scratch (no allocation allowed) ----------------
__device__ __half g_patch[MP_ * D_];
__device__ float  g_x[MP_ * D_];
__device__ __half g_ln[MP_ * D_];
__device__ __half g_qkv[MP_ * 3 * D_];
__device__ __half g_att[MP_ * D_];
__device__ __half g_ff[MP_ * FF_];        // MLP hidden; also f32 conv scratch
// fp16 weight copies
__device__ __half w_qkv[L_ * 3 * D_ * D_];
__device__ __half w_out[L_ * D_ * D_];
__device__ __half w_fc[L_ * FF_ * D_];
__device__ __half w_pr[L_ * D_ * FF_];
__device__ __half w_conv[D_ * D_];

// ---------------- helpers ----------------
__device__ __forceinline__ float gelu_exact(float v) {
    return 0.5f * v * (1.0f + erff(v * 0.70710678118654752f));
}
#define CP_ASYNC16(dst, src) \
    asm volatile("cp.async.cg.shared.global [%0], [%1], 16;\n" :: "r"(dst), "l"(src))
#define CP_COMMIT() asm volatile("cp.async.commit_group;\n" ::: "memory")
#define CP_WAIT1()  asm volatile("cp.async.wait_group 1;\n" ::: "memory")

__device__ __forceinline__ uint32_t smem_u32(const void* p) {
    uint32_t a;
    asm("{ .reg .u64 t; cvta.to.shared.u64 t, %1; cvt.u32.u64 %0, t; }" : "=r"(a) : "l"(p));
    return a;
}
__device__ __forceinline__ void mma_f16(float* c, const uint32_t* a, const uint32_t* b) {
    asm volatile(
        "mma.sync.aligned.m16n8k16.row.col.f32.f16.f16.f32 "
        "{%0,%1,%2,%3}, {%4,%5,%6,%7}, {%8,%9}, {%0,%1,%2,%3};"
        : "+f"(c[0]), "+f"(c[1]), "+f"(c[2]), "+f"(c[3])
        : "r"(a[0]), "r"(a[1]), "r"(a[2]), "r"(a[3]), "r"(b[0]), "r"(b[1]));
}
#define LDSM4(r, a) \
    asm volatile("ldmatrix.sync.aligned.m8n8.x4.shared.b16 {%0,%1,%2,%3}, [%4];" \
        : "=r"((r)[0]), "=r"((r)[1]), "=r"((r)[2]), "=r"((r)[3]) : "r"(a))

__device__ __forceinline__ uint32_t h2_u32(__half2 h) {
    return *reinterpret_cast<uint32_t*>(&h);
}

// ---------------- f32 -> f16 weight conversion ----------------
__global__ void f2h_kernel(const float4* __restrict__ s, __half* __restrict__ d, int n8) {
    int i = blockIdx.x * 256 + threadIdx.x;
    if (i >= n8) return;
    float4 a = s[i * 2], b = s[i * 2 + 1];
    uint4 u;
    u.x = h2_u32(__floats2half2_rn(a.x, a.y));
    u.y = h2_u32(__floats2half2_rn(a.z, a.w));
    u.z = h2_u32(__floats2half2_rn(b.x, b.y));
    u.w = h2_u32(__floats2half2_rn(b.z, b.w));
    *reinterpret_cast<uint4*>(d + (size_t)i * 8) = u;
}

// ---------------- fp16 tensor-core GEMM: C = A[M,K] * W[N,K]^T ----------------
// block tile 128x128x64, 8 warps (4x2), warp tile 32x64, m16n8k16 f16 MMA
// 3-stage cp.async pipeline (32KB/stage -> 2 CTAs per SM), XOR-swizzled smem
#define STAGE_BYTES 32768u
#define GSMEM_BYTES (3 * 32768)

template <int MODE, bool HOUT>
__global__ void __launch_bounds__(256, 2) gemm_tc(
    const __half* __restrict__ A, const __half* __restrict__ W,
    const float* __restrict__ bias, const float* __restrict__ res,
    void* __restrict__ Cv, int N, int K)
{
    extern __shared__ float smem[];
    uint32_t sbase = smem_u32(smem);
    int tid = threadIdx.x;
    int wid = tid >> 5, lane = tid & 31;
    int g = lane >> 2, t = lane & 3;
    int warpM = wid & 3, warpN = wid >> 2;

    int row0 = blockIdx.x * 128;
    int col0 = blockIdx.y * 128;
    const __half* Abase = A + (size_t)row0 * K;
    const __half* Wbase = W + (size_t)col0 * K;

    auto load_stage = [&](int s, int k0) {
        uint32_t ab = sbase + (uint32_t)s * STAGE_BYTES;
        uint32_t bb = ab + 16384u;
        #pragma unroll
        for (int i = 0; i < 4; i++) {
            int idx = tid + i * 256;
            int r = idx >> 3, c = idx & 7;
            uint32_t d = ab + (uint32_t)(r * 128 + ((c ^ (r & 7)) * 16));
            CP_ASYNC16(d, Abase + (size_t)r * K + k0 + c * 8);
        }
        #pragma unroll
        for (int i = 0; i < 4; i++) {
            int idx = tid + i * 256;
            int r = idx >> 3, c = idx & 7;
            uint32_t d = bb + (uint32_t)(r * 128 + ((c ^ (r & 7)) * 16));
            CP_ASYNC16(d, Wbase + (size_t)r * K + k0 + c * 8);
        }
        CP_COMMIT();
    };

    float acc[2][8][4];
    #pragma unroll
    for (int i = 0; i < 2; i++)
        #pragma unroll
        for (int j = 0; j < 8; j++)
            #pragma unroll
            for (int r = 0; r < 4; r++) acc[i][j][r] = 0.f;

    int ar = lane & 15;
    int asel = lane >> 4;
    int brr = (lane & 7) + ((lane >> 4) << 3);
    int bsel = (lane >> 3) & 1;
    uint32_t aRow[2], bRow[4], aChunk[4], bChunk[4];
    #pragma unroll
    for (int mt = 0; mt < 2; mt++)
        aRow[mt] = (uint32_t)((warpM * 32 + mt * 16 + ar) * 128);
    #pragma unroll
    for (int nt2 = 0; nt2 < 4; nt2++)
        bRow[nt2] = (uint32_t)((warpN * 64 + nt2 * 16 + brr) * 128);
    #pragma unroll
    for (int kt = 0; kt < 4; kt++) {
        aChunk[kt] = (uint32_t)((((kt * 2 + asel) ^ (lane & 7)) * 16));
        bChunk[kt] = (uint32_t)((((kt * 2 + bsel) ^ (lane & 7)) * 16));
    }

    int nIter = K >> 6;
    load_stage(0, 0);
    load_stage(1, 64);

    for (int it = 0; it < nIter; it++) {
        CP_WAIT1();
        __syncthreads();
        if (it + 2 < nIter) load_stage((it + 2) % 3, (it + 2) * 64);
        else CP_COMMIT();

        uint32_t ab = sbase + (uint32_t)(it % 3) * STAGE_BYTES;
        uint32_t bb = ab + 16384u;
        #pragma unroll
        for (int kt = 0; kt < 4; kt++) {
            uint32_t af[2][4], bf[4][4];
            #pragma unroll
            for (int mt = 0; mt < 2; mt++)
                LDSM4(af[mt], ab + aRow[mt] + aChunk[kt]);
            #pragma unroll
            for (int nt2 = 0; nt2 < 4; nt2++)
                LDSM4(bf[nt2], bb + bRow[nt2] + bChunk[kt]);
            #pragma unroll
            for (int mt = 0; mt < 2; mt++)
                #pragma unroll
                for (int nt2 = 0; nt2 < 4; nt2++) {
                    mma_f16(acc[mt][nt2 * 2],     af[mt], &bf[nt2][0]);
                    mma_f16(acc[mt][nt2 * 2 + 1], af[mt], &bf[nt2][2]);
                }
        }
    }

    #pragma unroll
    for (int nt = 0; nt < 8; nt++) {
        int col = col0 + warpN * 64 + nt * 8 + 2 * t;
        float2 bv = make_float2(0.f, 0.f);
        if (bias) bv = *(const float2*)(bias + col);
        #pragma unroll
        for (int mt = 0; mt < 2; mt++) {
            int row = row0 + warpM * 32 + mt * 16 + g;
            #pragma unroll
            for (int half_ = 0; half_ < 2; half_++) {
                int r = row + half_ * 8;
                float2 v;
                v.x = acc[mt][nt][half_ * 2 + 0] + bv.x;
                v.y = acc[mt][nt][half_ * 2 + 1] + bv.y;
                if (MODE == 1) {
                    float2 rv = *(const float2*)(res + (size_t)r * N + col);
                    v.x += rv.x; v.y += rv.y;
                }
                if (MODE == 2) { v.x = gelu_exact(v.x); v.y = gelu_exact(v.y); }
                if (HOUT) {
                    *reinterpret_cast<__half2*>((__half*)Cv + (size_t)r * N + col) =
                        __floats2half2_rn(v.x, v.y);
                } else {
                    *(float2*)((float*)Cv + (size_t)r * N + col) = v;
                }
            }
        }
    }
}

// ---------------- 64x128 tile variant (wave-friendly) ----------------
// 8 warps (2x4), warp tile 32x32, stage 24KB x 3 -> 2 CTAs/SM.
#define STAGE64 24576u
#define GSMEM64 (3 * 24576)

template <int MODE, bool HOUT>
__global__ void __launch_bounds__(256, 2) gemm64(
    const __half* __restrict__ A, const __half* __restrict__ W,
    const float* __restrict__ bias, const float* __restrict__ res,
    void* __restrict__ Cv, int N, int K)
{
    extern __shared__ float smem[];
    uint32_t sbase = smem_u32(smem);
    int tid = threadIdx.x;
    int wid = tid >> 5, lane = tid & 31;
    int g = lane >> 2, t = lane & 3;
    int warpM = wid & 1, warpN = wid >> 1;       // 2 x 4 warp grid

    int row0 = blockIdx.x * 64;
    int col0 = blockIdx.y * 128;
    const __half* Abase = A + (size_t)row0 * K;
    const __half* Wbase = W + (size_t)col0 * K;

    auto load_stage = [&](int s, int k0) {
        uint32_t ab = sbase + (uint32_t)s * STAGE64;
        uint32_t bb = ab + 8192u;
        #pragma unroll
        for (int i = 0; i < 2; i++) {   // A: 64 rows x 8 chunks = 512
            int idx = tid + i * 256;
            int r = idx >> 3, c = idx & 7;
            uint32_t d = ab + (uint32_t)(r * 128 + ((c ^ (r & 7)) * 16));
            CP_ASYNC16(d, Abase + (size_t)r * K + k0 + c * 8);
        }
        #pragma unroll
        for (int i = 0; i < 4; i++) {   // B: 128 rows x 8 chunks = 1024
            int idx = tid + i * 256;
            int r = idx >> 3, c = idx & 7;
            uint32_t d = bb + (uint32_t)(r * 128 + ((c ^ (r & 7)) * 16));
            CP_ASYNC16(d, Wbase + (size_t)r * K + k0 + c * 8);
        }
        CP_COMMIT();
    };

    float acc[2][4][4];
    #pragma unroll
    for (int i = 0; i < 2; i++)
        #pragma unroll
        for (int j = 0; j < 4; j++)
            #pragma unroll
            for (int r = 0; r < 4; r++) acc[i][j][r] = 0.f;

    int ar = lane & 15;
    int asel = lane >> 4;
    int brr = (lane & 7) + ((lane >> 4) << 3);
    int bsel = (lane >> 3) & 1;
    uint32_t aRow[2], bRow[2], aChunk[4], bChunk[4];
    #pragma unroll
    for (int mt = 0; mt < 2; mt++)
        aRow[mt] = (uint32_t)((warpM * 32 + mt * 16 + ar) * 128);
    #pragma unroll
    for (int nt2 = 0; nt2 < 2; nt2++)
        bRow[nt2] = (uint32_t)((warpN * 32 + nt2 * 16 + brr) * 128);
    #pragma unroll
    for (int kt = 0; kt < 4; kt++) {
        aChunk[kt] = (uint32_t)((((kt * 2 + asel) ^ (lane & 7)) * 16));
        bChunk[kt] = (uint32_t)((((kt * 2 + bsel) ^ (lane & 7)) * 16));
    }

    int nIter = K >> 6;
    load_stage(0, 0);
    load_stage(1, 64);

    for (int it = 0; it < nIter; it++) {
        CP_WAIT1();
        __syncthreads();
        if (it + 2 < nIter) load_stage((it + 2) % 3, (it + 2) * 64);
        else CP_COMMIT();

        uint32_t ab = sbase + (uint32_t)(it % 3) * STAGE64;
        uint32_t bb = ab + 8192u;
        #pragma unroll
        for (int kt = 0; kt < 4; kt++) {
            uint32_t af[2][4], bf[2][4];
            #pragma unroll
            for (int mt = 0; mt < 2; mt++)
                LDSM4(af[mt], ab + aRow[mt] + aChunk[kt]);
            #pragma unroll
            for (int nt2 = 0; nt2 < 2; nt2++)
                LDSM4(bf[nt2], bb + bRow[nt2] + bChunk[kt]);
            #pragma unroll
            for (int mt = 0; mt < 2; mt++)
                #pragma unroll
                for (int nt2 = 0; nt2 < 2; nt2++) {
                    mma_f16(acc[mt][nt2 * 2],     af[mt], &bf[nt2][0]);
                    mma_f16(acc[mt][nt2 * 2 + 1], af[mt], &bf[nt2][2]);
                }
        }
    }

    #pragma unroll
    for (int nt = 0; nt < 4; nt++) {
        int col = col0 + warpN * 32 + nt * 8 + 2 * t;
        float2 bv = make_float2(0.f, 0.f);
        if (bias) bv = *(const float2*)(bias + col);
        #pragma unroll
        for (int mt = 0; mt < 2; mt++) {
            int row = row0 + warpM * 32 + mt * 16 + g;
            #pragma unroll
            for (int half_ = 0; half_ < 2; half_++) {
                int r = row + half_ * 8;
                float2 v;
                v.x = acc[mt][nt][half_ * 2 + 0] + bv.x;
                v.y = acc[mt][nt][half_ * 2 + 1] + bv.y;
                if (MODE == 1) {
                    float2 rv = *(const float2*)(res + (size_t)r * N + col);
                    v.x += rv.x; v.y += rv.y;
                }
                if (MODE == 2) { v.x = gelu_exact(v.x); v.y = gelu_exact(v.y); }
                if (HOUT) {
                    *reinterpret_cast<__half2*>((__half*)Cv + (size_t)r * N + col) =
                        __floats2half2_rn(v.x, v.y);
                } else {
                    *(float2*)((float*)Cv + (size_t)r * N + col) = v;
                }
            }
        }
    }
}

// ---------------- patchify (im2col gather -> fp16) ----------------
__global__ void patchify_kernel(const float* __restrict__ img) {
    int idx = blockIdx.x * 256 + threadIdx.x;
    if (idx >= B_ * NP_ * D_) return;
    int k = idx % D_;
    int bp = idx / D_;
    int p = bp % NP_;
    int b = bp / NP_;
    int c = k >> 8;
    int rem = k & 255;
    int dy = rem >> 4, dx = rem & 15;
    int y = (p / 14) * P_ + dy;
    int x = (p % 14) * P_ + dx;
    g_patch[idx] = __float2half(img[(((size_t)b * 3 + c) * IMG_ + y) * IMG_ + x]);
}

// ---------------- reductions ----------------
__device__ __forceinline__ void block_sum2(float& a, float& b, float* sm) {
    #pragma unroll
    for (int o = 16; o; o >>= 1) {
        a += __shfl_xor_sync(0xffffffffu, a, o);
        b += __shfl_xor_sync(0xffffffffu, b, o);
    }
    int warp = threadIdx.x >> 5, lane = threadIdx.x & 31;
    int nw = blockDim.x >> 5;
    if (lane == 0) { sm[warp] = a; sm[warp + 8] = b; }
    __syncthreads();
    if (threadIdx.x == 0) {
        float sa = 0.f, sb = 0.f;
        for (int i = 0; i < nw; i++) { sa += sm[i]; sb += sm[i + 8]; }
        sm[0] = sa; sm[8] = sb;
    }
    __syncthreads();
    a = sm[0]; b = sm[8];
    __syncthreads();
}
__device__ __forceinline__ float block_sum(float v, float* sm) {
    #pragma unroll
    for (int o = 16; o; o >>= 1) v += __shfl_xor_sync(0xffffffffu, v, o);
    int warp = threadIdx.x >> 5, lane = threadIdx.x & 31;
    int nw = blockDim.x >> 5;
    if (lane == 0) sm[warp] = v;
    __syncthreads();
    if (threadIdx.x == 0) {
        float s = 0.f;
        for (int i = 0; i < nw; i++) s += sm[i];
        sm[0] = s;
    }
    __syncthreads();
    v = sm[0];
    __syncthreads();
    return v;
}

// ---------------- embed + ln_pre (conv output read from g_ff-as-f32) --------
__global__ void __launch_bounds__(256) embed_ln_kernel(
    const float* __restrict__ cls_emb, const float* __restrict__ pos_emb,
    const float* __restrict__ w, const float* __restrict__ bb)
{
    __shared__ float sm[16];
    const float* conv = (const float*)g_ff;
    int row = blockIdx.x;
    int b = row / SEQ_, s = row % SEQ_;
    int tid = threadIdx.x;
    float v[3];
    #pragma unroll
    for (int i = 0; i < 3; i++) {
        int d = tid + i * 256;
        float base = (s == 0) ? cls_emb[d]
                              : conv[((size_t)(b * NP_ + (s - 1))) * D_ + d];
        v[i] = base + pos_emb[(size_t)s * D_ + d];
    }
    float sum = v[0] + v[1] + v[2];
    float sq = v[0] * v[0] + v[1] * v[1] + v[2] * v[2];
    block_sum2(sum, sq, sm);
    float mean = sum * (1.0f / D_);
    float var = sq * (1.0f / D_) - mean * mean;
    float r = rsqrtf(var + 1e-5f);
    #pragma unroll
    for (int i = 0; i < 3; i++) {
        int d = tid + i * 256;
        g_x[(size_t)row * D_ + d] = (v[i] - mean) * r * w[d] + bb[d];
    }
}

// ---------------- layernorm v2: warp per row, 8 rows per block --------------
__global__ void __launch_bounds__(256) ln_kernel(
    const float* __restrict__ x, __half* __restrict__ y,
    const float* __restrict__ w, const float* __restrict__ bb)
{
    int row = blockIdx.x * 8 + (threadIdx.x >> 5);
    int lane = threadIdx.x & 31;
    const float4* xr = (const float4*)(x + (size_t)row * D_);
    float4 v[6];
    float sum = 0.f, sq = 0.f;
    #pragma unroll
    for (int j = 0; j < 6; j++) {
        v[j] = xr[lane + j * 32];
        sum += v[j].x + v[j].y + v[j].z + v[j].w;
        sq += v[j].x * v[j].x + v[j].y * v[j].y + v[j].z * v[j].z + v[j].w * v[j].w;
    }
    #pragma unroll
    for (int o = 16; o; o >>= 1) {
        sum += __shfl_xor_sync(0xffffffffu, sum, o);
        sq  += __shfl_xor_sync(0xffffffffu, sq, o);
    }
    float mean = sum * (1.0f / D_);
    float var = sq * (1.0f / D_) - mean * mean;
    float r = rsqrtf(var + 1e-5f);
    __half2* yr = (__half2*)(y + (size_t)row * D_);
    const float4* w4 = (const float4*)w;
    const float4* b4 = (const float4*)bb;
    #pragma unroll
    for (int j = 0; j < 6; j++) {
        int idx = lane + j * 32;
        float4 wv = w4[idx], bv = b4[idx];
        float o0 = (v[j].x - mean) * r * wv.x + bv.x;
        float o1 = (v[j].y - mean) * r * wv.y + bv.y;
        float o2 = (v[j].z - mean) * r * wv.z + bv.z;
        float o3 = (v[j].w - mean) * r * wv.w + bv.w;
        yr[idx * 2]     = __floats2half2_rn(o0, o1);
        yr[idx * 2 + 1] = __floats2half2_rn(o2, o3);
    }
}

// ---------------- tensor-core attention ----------------
#define TQA   64
#define SKP   208
#define NTS   26
#define AQOFF 0u
#define AKOFF 8192u
#define APOFF 0u
#define AVOFF 32768u
#define ASMEM_BYTES 65536

__global__ void __launch_bounds__(128) attn3_kernel() {
    extern __shared__ char asmem[];
    uint32_t sb = smem_u32(asmem);
    int tid = threadIdx.x, wid = tid >> 5, lane = tid & 31;
    int g = lane >> 2, t = lane & 3;
    int q0 = blockIdx.x * TQA;
    int bh = blockIdx.y;
    int b = bh / H_, h = bh % H_;
    const __half* qkvb = g_qkv + (size_t)(b * SEQ_) * (3 * D_) + h * HD_;

    __half2 sc2 = __floats2half2_rn(0.125f, 0.125f);
    for (int i = tid; i < TQA * 8; i += 128) {
        int r = i >> 3, c = i & 7;
        uint4 u = make_uint4(0, 0, 0, 0);
        if (q0 + r < SEQ_)
            u = *(const uint4*)(qkvb + (size_t)(q0 + r) * (3 * D_) + c * 8);
        __half2* hp = (__half2*)&u;
        hp[0] = __hmul2(hp[0], sc2); hp[1] = __hmul2(hp[1], sc2);
        hp[2] = __hmul2(hp[2], sc2); hp[3] = __hmul2(hp[3], sc2);
        *(uint4*)(asmem + AQOFF + r * 128 + ((c ^ (r & 7)) * 16)) = u;
    }
    for (int i = tid; i < SKP * 8; i += 128) {
        int r = i >> 3, c = i & 7;
        uint4 u = make_uint4(0, 0, 0, 0);
        if (r < SEQ_)
            u = *(const uint4*)(qkvb + D_ + (size_t)r * (3 * D_) + c * 8);
        *(uint4*)(asmem + AKOFF + r * 128 + ((c ^ (r & 7)) * 16)) = u;
    }
    __syncthreads();

    int ar = lane & 15;
    int asel = lane >> 4;
    int brr = (lane & 7) + ((lane >> 4) << 3);
    int bsel = (lane >> 3) & 1;
    int l7 = lane & 7;

    uint32_t qf[4][4];
    #pragma unroll
    for (int kc = 0; kc < 4; kc++) {
        uint32_t c = kc * 2 + asel;
        LDSM4(qf[kc], sb + AQOFF + (uint32_t)((wid * 16 + ar) * 128) + ((c ^ l7) & 7) * 16);
    }
    float sacc[NTS][4];
    #pragma unroll
    for (int nt = 0; nt < NTS; nt++)
        #pragma unroll
        for (int r = 0; r < 4; r++) sacc[nt][r] = 0.f;

    #pragma unroll
    for (int kc = 0; kc < 4; kc++) {
        uint32_t cb = kc * 2 + bsel;
        uint32_t cboff = ((cb ^ l7) & 7) * 16;
        #pragma unroll
        for (int n16 = 0; n16 < 13; n16++) {
            uint32_t bf[4];
            LDSM4(bf, sb + AKOFF + (uint32_t)((n16 * 16 + brr) * 128) + cboff);
            mma_f16(sacc[n16 * 2],     qf[kc], &bf[0]);
            mma_f16(sacc[n16 * 2 + 1], qf[kc], &bf[2]);
        }
    }

    float mx0 = -1e30f, mx1 = -1e30f;
    #pragma unroll
    for (int nt = 0; nt < NTS; nt++) {
        int c0 = nt * 8 + 2 * t;
        if (c0 >= SEQ_)     { sacc[nt][0] = -1e30f; sacc[nt][2] = -1e30f; }
        if (c0 + 1 >= SEQ_) { sacc[nt][1] = -1e30f; sacc[nt][3] = -1e30f; }
        mx0 = fmaxf(mx0, fmaxf(sacc[nt][0], sacc[nt][1]));
        mx1 = fmaxf(mx1, fmaxf(sacc[nt][2], sacc[nt][3]));
    }
    mx0 = fmaxf(mx0, __shfl_xor_sync(0xffffffffu, mx0, 1));
    mx0 = fmaxf(mx0, __shfl_xor_sync(0xffffffffu, mx0, 2));
    mx1 = fmaxf(mx1, __shfl_xor_sync(0xffffffffu, mx1, 1));
    mx1 = fmaxf(mx1, __shfl_xor_sync(0xffffffffu, mx1, 2));
    float s0 = 0.f, s1 = 0.f;
    #pragma unroll
    for (int nt = 0; nt < NTS; nt++) {
        sacc[nt][0] = expf(sacc[nt][0] - mx0); s0 += sacc[nt][0];
        sacc[nt][1] = expf(sacc[nt][1] - mx0); s0 += sacc[nt][1];
        sacc[nt][2] = expf(sacc[nt][2] - mx1); s1 += sacc[nt][2];
        sacc[nt][3] = expf(sacc[nt][3] - mx1); s1 += sacc[nt][3];
    }
    s0 += __shfl_xor_sync(0xffffffffu, s0, 1);
    s0 += __shfl_xor_sync(0xffffffffu, s0, 2);
    s1 += __shfl_xor_sync(0xffffffffu, s1, 1);
    s1 += __shfl_xor_sync(0xffffffffu, s1, 2);
    float inv0 = 1.0f / s0, inv1 = 1.0f / s1;

    __syncthreads();

    {
        int row0 = wid * 16 + g;
        #pragma unroll
        for (int nt = 0; nt < NTS; nt++) {
            uint32_t sw = (uint32_t)((nt & 24) | ((nt ^ g) & 7));
            *(__half2*)(asmem + APOFF + row0 * 512 + sw * 16 + t * 4) =
                __floats2half2_rn(sacc[nt][0] * inv0, sacc[nt][1] * inv0);
            *(__half2*)(asmem + APOFF + (row0 + 8) * 512 + sw * 16 + t * 4) =
                __floats2half2_rn(sacc[nt][2] * inv1, sacc[nt][3] * inv1);
        }
    }
    for (int rp = tid; rp * 2 < SKP; rp += 128) {
        int r0v = rp * 2, r1v = rp * 2 + 1;
        uint4 u0[8], u1[8];
        if (r0v < SEQ_) {
            const uint4* vp = (const uint4*)(qkvb + 2 * D_ + (size_t)r0v * (3 * D_));
            #pragma unroll
            for (int j = 0; j < 8; j++) u0[j] = vp[j];
        } else {
            #pragma unroll
            for (int j = 0; j < 8; j++) u0[j] = make_uint4(0, 0, 0, 0);
        }
        if (r1v < SEQ_) {
            const uint4* vp = (const uint4*)(qkvb + 2 * D_ + (size_t)r1v * (3 * D_));
            #pragma unroll
            for (int j = 0; j < 8; j++) u1[j] = vp[j];
        } else {
            #pragma unroll
            for (int j = 0; j < 8; j++) u1[j] = make_uint4(0, 0, 0, 0);
        }
        const __half* h0 = (const __half*)u0;
        const __half* h1 = (const __half*)u1;
        int cchunk = r0v >> 3, rin = r0v & 7;
        #pragma unroll
        for (int hd = 0; hd < 64; hd++) {
            uint32_t sw = (uint32_t)((cchunk & 24) | ((cchunk ^ (hd & 7)) & 7));
            *(__half2*)(asmem + AVOFF + hd * 512 + sw * 16 + rin * 2) =
                __halves2half2(h0[hd], h1[hd]);
        }
    }
    __syncthreads();

    float oacc[8][4];
    #pragma unroll
    for (int i = 0; i < 8; i++)
        #pragma unroll
        for (int r = 0; r < 4; r++) oacc[i][r] = 0.f;

    uint32_t aRowP = (uint32_t)((wid * 16 + ar) * 512);
    #pragma unroll
    for (int kc = 0; kc < 13; kc++) {
        uint32_t ca = (uint32_t)(kc * 2 + asel);
        uint32_t pf[4];
        LDSM4(pf, sb + APOFF + aRowP + ((ca & 24) | ((ca ^ (uint32_t)l7) & 7)) * 16);
        uint32_t cb = (uint32_t)(kc * 2 + bsel);
        uint32_t cboff = ((cb & 24) | ((cb ^ (uint32_t)l7) & 7)) * 16;
        #pragma unroll
        for (int n16 = 0; n16 < 4; n16++) {
            uint32_t vf[4];
            LDSM4(vf, sb + AVOFF + (uint32_t)((n16 * 16 + brr) * 512) + cboff);
            mma_f16(oacc[n16 * 2],     pf, &vf[0]);
            mma_f16(oacc[n16 * 2 + 1], pf, &vf[2]);
        }
    }

    #pragma unroll
    for (int nt = 0; nt < 8; nt++) {
        int col = h * HD_ + nt * 8 + 2 * t;
        int r0 = q0 + wid * 16 + g;
        if (r0 < SEQ_)
            *(__half2*)(g_att + (size_t)(b * SEQ_ + r0) * D_ + col) =
                __floats2half2_rn(oacc[nt][0], oacc[nt][1]);
        int r1 = r0 + 8;
        if (r1 < SEQ_)
            *(__half2*)(g_att + (size_t)(b * SEQ_ + r1) * D_ + col) =
                __floats2half2_rn(oacc[nt][2], oacc[nt][3]);
    }
}

// ---------------- final head ----------------
__global__ void __launch_bounds__(256) head_kernel(
    const float* __restrict__ w, const float* __restrict__ bb,
    const float* __restrict__ proj, float* __restrict__ out)
{
    __shared__ float cls[D_];
    __shared__ float feats[E_];
    __shared__ float sm[16];
    int b = blockIdx.x;
    int tid = threadIdx.x;
    const float* xr = g_x + (size_t)(b * SEQ_) * D_;
    float v[3];
    #pragma unroll
    for (int i = 0; i < 3; i++) v[i] = xr[tid + i * 256];
    float sum = v[0] + v[1] + v[2];
    float sq = v[0] * v[0] + v[1] * v[1] + v[2] * v[2];
    block_sum2(sum, sq, sm);
    float mean = sum * (1.0f / D_);
    float var = sq * (1.0f / D_) - mean * mean;
    float r = rsqrtf(var + 1e-5f);
    #pragma unroll
    for (int i = 0; i < 3; i++) {
        int d = tid + i * 256;
        cls[d] = (v[i] - mean) * r * w[d] + bb[d];
    }
    __syncthreads();
    for (int e = tid; e < E_; e += 256) {
        float a = 0.f;
        for (int d = 0; d < D_; d++) a += cls[d] * proj[(size_t)d * E_ + e];
        feats[e] = a;
    }
    __syncthreads();
    float nrm = 0.f;
    for (int e = tid; e < E_; e += 256) nrm += feats[e] * feats[e];
    nrm = block_sum(nrm, sm);
    float rn = rsqrtf(nrm);
    for (int e = tid; e < E_; e += 256) out[(size_t)b * E_ + e] = feats[e] * rn;
}

// ---------------- host ----------------
extern "C" void kernel_launch(void* const* d_in, const int* in_sizes, int n_in,
                              void* d_out, int out_size)
{
    const float* image     = (const float*)d_in[0];
    const float* conv_w    = (const float*)d_in[1];
    const float* cls_emb   = (const float*)d_in[2];
    const float* pos_emb   = (const float*)d_in[3];
    const float* ln_pre_w  = (const float*)d_in[4];
    const float* ln_pre_b  = (const float*)d_in[5];
    const float* ln1_w     = (const float*)d_in[6];
    const float* ln1_b     = (const float*)d_in[7];
    const float* qkv_w     = (const float*)d_in[8];
    const float* qkv_b     = (const float*)d_in[9];
    const float* out_w     = (const float*)d_in[10];
    const float* out_b     = (const float*)d_in[11];
    const float* ln2_w     = (const float*)d_in[12];
    const float* ln2_b     = (const float*)d_in[13];
    const float* fc_w      = (const float*)d_in[14];
    const float* fc_b      = (const float*)d_in[15];
    const float* pr_w      = (const float*)d_in[16];
    const float* pr_b      = (const float*)d_in[17];
    const float* ln_post_w = (const float*)d_in[18];
    const float* ln_post_b = (const float*)d_in[19];
    const float* proj      = (const float*)d_in[20];
    float* out = (float*)d_out;
    (void)in_sizes; (void)n_in; (void)out_size;

    __half *p_patch, *p_ln, *p_att, *p_ff, *p_qkv;
    float  *p_x;
    __half *pw_qkv, *pw_out, *pw_fc, *pw_pr, *pw_conv;
    cudaGetSymbolAddress((void**)&p_patch, g_patch);
    cudaGetSymbolAddress((void**)&p_x,     g_x);
    cudaGetSymbolAddress((void**)&p_ln,    g_ln);
    cudaGetSymbolAddress((void**)&p_qkv,   g_qkv);
    cudaGetSymbolAddress((void**)&p_att,   g_att);
    cudaGetSymbolAddress((void**)&p_ff,    g_ff);
    cudaGetSymbolAddress((void**)&pw_qkv,  w_qkv);
    cudaGetSymbolAddress((void**)&pw_out,  w_out);
    cudaGetSymbolAddress((void**)&pw_fc,   w_fc);
    cudaGetSymbolAddress((void**)&pw_pr,   w_pr);
    cudaGetSymbolAddress((void**)&pw_conv, w_conv);
    float* p_conv = (float*)p_ff;   // f32 conv scratch aliases g_ff

    cudaFuncSetAttribute(gemm_tc<0, false>, cudaFuncAttributeMaxDynamicSharedMemorySize, GSMEM_BYTES);
    cudaFuncSetAttribute(gemm64<0, true>,  cudaFuncAttributeMaxDynamicSharedMemorySize, GSMEM64);
    cudaFuncSetAttribute(gemm64<1, false>, cudaFuncAttributeMaxDynamicSharedMemorySize, GSMEM64);
    cudaFuncSetAttribute(gemm64<2, true>,  cudaFuncAttributeMaxDynamicSharedMemorySize, GSMEM64);
    cudaFuncSetAttribute(attn3_kernel, cudaFuncAttributeMaxDynamicSharedMemorySize, ASMEM_BYTES);

    auto cvt = [&](const float* s, __half* d, int n) {
        f2h_kernel<<<(n / 8 + 255) / 256, 256>>>((const float4*)s, d, n / 8);
    };
    cvt(qkv_w, pw_qkv, L_ * 3 * D_ * D_);
    cvt(out_w, pw_out, L_ * D_ * D_);
    cvt(fc_w,  pw_fc,  L_ * FF_ * D_);
    cvt(pr_w,  pw_pr,  L_ * D_ * FF_);
    cvt(conv_w, pw_conv, D_ * D_);

    const int MT = MP_ / 128;    // 50
    const int MT64 = MP_ / 64;   // 100
    const int LNB = NTOK / 8;    // 788

    patchify_kernel<<<(B_ * NP_ * D_ + 255) / 256, 256>>>(image);
    gemm_tc<0, false><<<dim3(MT, D_ / 128), 256, GSMEM_BYTES>>>(
        p_patch, pw_conv, nullptr, nullptr, p_conv, D_, D_);
    embed_ln_kernel<<<NTOK, 256>>>(cls_emb, pos_emb, ln_pre_w, ln_pre_b);

    for (int l = 0; l < L_; l++) {
        ln_kernel<<<LNB, 256>>>(p_x, p_ln, ln1_w + l * D_, ln1_b + l * D_);
        gemm64<0, true><<<dim3(MT64, 3 * D_ / 128), 256, GSMEM64>>>(
            p_ln, pw_qkv + (size_t)l * 3 * D_ * D_, qkv_b + (size_t)l * 3 * D_,
            nullptr, p_qkv, 3 * D_, D_);
        attn3_kernel<<<dim3((SEQ_ + TQA - 1) / TQA, B_ * H_), 128, ASMEM_BYTES>>>();
        gemm64<1, false><<<dim3(MT64, D_ / 128), 256, GSMEM64>>>(
            p_att, pw_out + (size_t)l * D_ * D_, out_b + (size_t)l * D_,
            p_x, p_x, D_, D_);
        ln_kernel<<<LNB, 256>>>(p_x, p_ln, ln2_w + l * D_, ln2_b + l * D_);
        gemm64<2, true><<<dim3(MT64, FF_ / 128), 256, GSMEM64>>>(
            p_ln, pw_fc + (size_t)l * FF_ * D_, fc_b + (size_t)l * FF_,
            nullptr, p_ff, FF_, D_);
        gemm64<1, false><<<dim3(MT64, D_ / 128), 256, GSMEM64>>>(
            p_ff, pw_pr + (size_t)l * D_ * FF_, pr_b + (size_t)l * D_,
            p_x, p_x, D_, FF_);
    }
    head_kernel<<<B_, 256>>>(ln_post_w, ln_post_b, proj, out);
}

// round 15
// speedup vs baseline: 1.0201x; 1.0201x over previous
#include <cuda_runtime.h>
#include <cuda_fp16.h>
#include <math.h>
#include <stdint.h>

// ---------------- problem constants ----------------
#define D_    768
#define H_    12
#define HD_   64
#define FF_   3072
#define SEQ_  197
#define B_    32
#define NTOK  (B_ * SEQ_)     // 6304
#define MP_   6400            // padded token rows (50 * 128)
#define L_    12
#define E_    512
#define NP_   196
#define IMG_  224
#define P_    16

// ---------------- device scratch (no allocation allowed) ----------------
__device__ __half g_patch[MP_ * D_];
__device__ float  g_x[MP_ * D_];
__device__ __half g_ln[MP_ * D_];
__device__ __half g_qkv[MP_ * 3 * D_];
__device__ __half g_att[MP_ * D_];
__device__ __half g_ff[MP_ * FF_];        // MLP hidden; also f32 conv scratch
// fp16 weight copies
__device__ __half w_qkv[L_ * 3 * D_ * D_];
__device__ __half w_out[L_ * D_ * D_];
__device__ __half w_fc[L_ * FF_ * D_];
__device__ __half w_pr[L_ * D_ * FF_];
__device__ __half w_conv[D_ * D_];

// ---------------- helpers ----------------
__device__ __forceinline__ float gelu_exact(float v) {
    return 0.5f * v * (1.0f + erff(v * 0.70710678118654752f));
}
#define CP_ASYNC16(dst, src) \
    asm volatile("cp.async.cg.shared.global [%0], [%1], 16;\n" :: "r"(dst), "l"(src))
#define CP_COMMIT() asm volatile("cp.async.commit_group;\n" ::: "memory")
#define CP_WAIT1()  asm volatile("cp.async.wait_group 1;\n" ::: "memory")

__device__ __forceinline__ uint32_t smem_u32(const void* p) {
    uint32_t a;
    asm("{ .reg .u64 t; cvta.to.shared.u64 t, %1; cvt.u32.u64 %0, t; }" : "=r"(a) : "l"(p));
    return a;
}
__device__ __forceinline__ void mma_f16(float* c, const uint32_t* a, const uint32_t* b) {
    asm volatile(
        "mma.sync.aligned.m16n8k16.row.col.f32.f16.f16.f32 "
        "{%0,%1,%2,%3}, {%4,%5,%6,%7}, {%8,%9}, {%0,%1,%2,%3};"
        : "+f"(c[0]), "+f"(c[1]), "+f"(c[2]), "+f"(c[3])
        : "r"(a[0]), "r"(a[1]), "r"(a[2]), "r"(a[3]), "r"(b[0]), "r"(b[1]));
}
#define LDSM4(r, a) \
    asm volatile("ldmatrix.sync.aligned.m8n8.x4.shared.b16 {%0,%1,%2,%3}, [%4];" \
        : "=r"((r)[0]), "=r"((r)[1]), "=r"((r)[2]), "=r"((r)[3]) : "r"(a))

__device__ __forceinline__ uint32_t h2_u32(__half2 h) {
    return *reinterpret_cast<uint32_t*>(&h);
}

// ---------------- f32 -> f16 weight conversion ----------------
__global__ void f2h_kernel(const float4* __restrict__ s, __half* __restrict__ d, int n8) {
    int i = blockIdx.x * 256 + threadIdx.x;
    if (i >= n8) return;
    float4 a = s[i * 2], b = s[i * 2 + 1];
    uint4 u;
    u.x = h2_u32(__floats2half2_rn(a.x, a.y));
    u.y = h2_u32(__floats2half2_rn(a.z, a.w));
    u.z = h2_u32(__floats2half2_rn(b.x, b.y));
    u.w = h2_u32(__floats2half2_rn(b.z, b.w));
    *reinterpret_cast<uint4*>(d + (size_t)i * 8) = u;
}

// ---------------- fp16 tensor-core GEMM: C = A[M,K] * W[N,K]^T ----------------
// block tile 128x128x64, 8 warps (4x2), warp tile 32x64, m16n8k16 f16 MMA
// 3-stage cp.async pipeline (32KB/stage -> 2 CTAs per SM), XOR-swizzled smem
#define STAGE_BYTES 32768u
#define GSMEM_BYTES (3 * 32768)

template <int MODE, bool HOUT>
__global__ void __launch_bounds__(256, 2) gemm_tc(
    const __half* __restrict__ A, const __half* __restrict__ W,
    const float* __restrict__ bias, const float* __restrict__ res,
    void* __restrict__ Cv, int N, int K)
{
    extern __shared__ float smem[];
    uint32_t sbase = smem_u32(smem);
    int tid = threadIdx.x;
    int wid = tid >> 5, lane = tid & 31;
    int g = lane >> 2, t = lane & 3;
    int warpM = wid & 3, warpN = wid >> 2;

    int row0 = blockIdx.x * 128;
    int col0 = blockIdx.y * 128;
    const __half* Abase = A + (size_t)row0 * K;
    const __half* Wbase = W + (size_t)col0 * K;

    auto load_stage = [&](int s, int k0) {
        uint32_t ab = sbase + (uint32_t)s * STAGE_BYTES;
        uint32_t bb = ab + 16384u;
        #pragma unroll
        for (int i = 0; i < 4; i++) {
            int idx = tid + i * 256;
            int r = idx >> 3, c = idx & 7;
            uint32_t d = ab + (uint32_t)(r * 128 + ((c ^ (r & 7)) * 16));
            CP_ASYNC16(d, Abase + (size_t)r * K + k0 + c * 8);
        }
        #pragma unroll
        for (int i = 0; i < 4; i++) {
            int idx = tid + i * 256;
            int r = idx >> 3, c = idx & 7;
            uint32_t d = bb + (uint32_t)(r * 128 + ((c ^ (r & 7)) * 16));
            CP_ASYNC16(d, Wbase + (size_t)r * K + k0 + c * 8);
        }
        CP_COMMIT();
    };

    float acc[2][8][4];
    #pragma unroll
    for (int i = 0; i < 2; i++)
        #pragma unroll
        for (int j = 0; j < 8; j++)
            #pragma unroll
            for (int r = 0; r < 4; r++) acc[i][j][r] = 0.f;

    int ar = lane & 15;
    int asel = lane >> 4;
    int brr = (lane & 7) + ((lane >> 4) << 3);
    int bsel = (lane >> 3) & 1;
    uint32_t aRow[2], bRow[4], aChunk[4], bChunk[4];
    #pragma unroll
    for (int mt = 0; mt < 2; mt++)
        aRow[mt] = (uint32_t)((warpM * 32 + mt * 16 + ar) * 128);
    #pragma unroll
    for (int nt2 = 0; nt2 < 4; nt2++)
        bRow[nt2] = (uint32_t)((warpN * 64 + nt2 * 16 + brr) * 128);
    #pragma unroll
    for (int kt = 0; kt < 4; kt++) {
        aChunk[kt] = (uint32_t)((((kt * 2 + asel) ^ (lane & 7)) * 16));
        bChunk[kt] = (uint32_t)((((kt * 2 + bsel) ^ (lane & 7)) * 16));
    }

    int nIter = K >> 6;
    load_stage(0, 0);
    load_stage(1, 64);

    for (int it = 0; it < nIter; it++) {
        CP_WAIT1();
        __syncthreads();
        if (it + 2 < nIter) load_stage((it + 2) % 3, (it + 2) * 64);
        else CP_COMMIT();

        uint32_t ab = sbase + (uint32_t)(it % 3) * STAGE_BYTES;
        uint32_t bb = ab + 16384u;
        #pragma unroll
        for (int kt = 0; kt < 4; kt++) {
            uint32_t af[2][4], bf[4][4];
            #pragma unroll
            for (int mt = 0; mt < 2; mt++)
                LDSM4(af[mt], ab + aRow[mt] + aChunk[kt]);
            #pragma unroll
            for (int nt2 = 0; nt2 < 4; nt2++)
                LDSM4(bf[nt2], bb + bRow[nt2] + bChunk[kt]);
            #pragma unroll
            for (int mt = 0; mt < 2; mt++)
                #pragma unroll
                for (int nt2 = 0; nt2 < 4; nt2++) {
                    mma_f16(acc[mt][nt2 * 2],     af[mt], &bf[nt2][0]);
                    mma_f16(acc[mt][nt2 * 2 + 1], af[mt], &bf[nt2][2]);
                }
        }
    }

    #pragma unroll
    for (int nt = 0; nt < 8; nt++) {
        int col = col0 + warpN * 64 + nt * 8 + 2 * t;
        float2 bv = make_float2(0.f, 0.f);
        if (bias) bv = *(const float2*)(bias + col);
        #pragma unroll
        for (int mt = 0; mt < 2; mt++) {
            int row = row0 + warpM * 32 + mt * 16 + g;
            #pragma unroll
            for (int half_ = 0; half_ < 2; half_++) {
                int r = row + half_ * 8;
                float2 v;
                v.x = acc[mt][nt][half_ * 2 + 0] + bv.x;
                v.y = acc[mt][nt][half_ * 2 + 1] + bv.y;
                if (MODE == 1) {
                    float2 rv = *(const float2*)(res + (size_t)r * N + col);
                    v.x += rv.x; v.y += rv.y;
                }
                if (MODE == 2) { v.x = gelu_exact(v.x); v.y = gelu_exact(v.y); }
                if (HOUT) {
                    *reinterpret_cast<__half2*>((__half*)Cv + (size_t)r * N + col) =
                        __floats2half2_rn(v.x, v.y);
                } else {
                    *(float2*)((float*)Cv + (size_t)r * N + col) = v;
                }
            }
        }
    }
}

// ---------------- 64x128 tile variant (wave-friendly, for out/pr) -----------
// 8 warps (2x4), warp tile 32x32, stage 24KB x 3 -> 2 CTAs/SM.
#define STAGE64 24576u
#define GSMEM64 (3 * 24576)

template <int MODE, bool HOUT>
__global__ void __launch_bounds__(256, 2) gemm64(
    const __half* __restrict__ A, const __half* __restrict__ W,
    const float* __restrict__ bias, const float* __restrict__ res,
    void* __restrict__ Cv, int N, int K)
{
    extern __shared__ float smem[];
    uint32_t sbase = smem_u32(smem);
    int tid = threadIdx.x;
    int wid = tid >> 5, lane = tid & 31;
    int g = lane >> 2, t = lane & 3;
    int warpM = wid & 1, warpN = wid >> 1;       // 2 x 4 warp grid

    int row0 = blockIdx.x * 64;
    int col0 = blockIdx.y * 128;
    const __half* Abase = A + (size_t)row0 * K;
    const __half* Wbase = W + (size_t)col0 * K;

    auto load_stage = [&](int s, int k0) {
        uint32_t ab = sbase + (uint32_t)s * STAGE64;
        uint32_t bb = ab + 8192u;
        #pragma unroll
        for (int i = 0; i < 2; i++) {   // A: 64 rows x 8 chunks = 512
            int idx = tid + i * 256;
            int r = idx >> 3, c = idx & 7;
            uint32_t d = ab + (uint32_t)(r * 128 + ((c ^ (r & 7)) * 16));
            CP_ASYNC16(d, Abase + (size_t)r * K + k0 + c * 8);
        }
        #pragma unroll
        for (int i = 0; i < 4; i++) {   // B: 128 rows x 8 chunks = 1024
            int idx = tid + i * 256;
            int r = idx >> 3, c = idx & 7;
            uint32_t d = bb + (uint32_t)(r * 128 + ((c ^ (r & 7)) * 16));
            CP_ASYNC16(d, Wbase + (size_t)r * K + k0 + c * 8);
        }
        CP_COMMIT();
    };

    float acc[2][4][4];
    #pragma unroll
    for (int i = 0; i < 2; i++)
        #pragma unroll
        for (int j = 0; j < 4; j++)
            #pragma unroll
            for (int r = 0; r < 4; r++) acc[i][j][r] = 0.f;

    int ar = lane & 15;
    int asel = lane >> 4;
    int brr = (lane & 7) + ((lane >> 4) << 3);
    int bsel = (lane >> 3) & 1;
    uint32_t aRow[2], bRow[2], aChunk[4], bChunk[4];
    #pragma unroll
    for (int mt = 0; mt < 2; mt++)
        aRow[mt] = (uint32_t)((warpM * 32 + mt * 16 + ar) * 128);
    #pragma unroll
    for (int nt2 = 0; nt2 < 2; nt2++)
        bRow[nt2] = (uint32_t)((warpN * 32 + nt2 * 16 + brr) * 128);
    #pragma unroll
    for (int kt = 0; kt < 4; kt++) {
        aChunk[kt] = (uint32_t)((((kt * 2 + asel) ^ (lane & 7)) * 16));
        bChunk[kt] = (uint32_t)((((kt * 2 + bsel) ^ (lane & 7)) * 16));
    }

    int nIter = K >> 6;
    load_stage(0, 0);
    load_stage(1, 64);

    for (int it = 0; it < nIter; it++) {
        CP_WAIT1();
        __syncthreads();
        if (it + 2 < nIter) load_stage((it + 2) % 3, (it + 2) * 64);
        else CP_COMMIT();

        uint32_t ab = sbase + (uint32_t)(it % 3) * STAGE64;
        uint32_t bb = ab + 8192u;
        #pragma unroll
        for (int kt = 0; kt < 4; kt++) {
            uint32_t af[2][4], bf[2][4];
            #pragma unroll
            for (int mt = 0; mt < 2; mt++)
                LDSM4(af[mt], ab + aRow[mt] + aChunk[kt]);
            #pragma unroll
            for (int nt2 = 0; nt2 < 2; nt2++)
                LDSM4(bf[nt2], bb + bRow[nt2] + bChunk[kt]);
            #pragma unroll
            for (int mt = 0; mt < 2; mt++)
                #pragma unroll
                for (int nt2 = 0; nt2 < 2; nt2++) {
                    mma_f16(acc[mt][nt2 * 2],     af[mt], &bf[nt2][0]);
                    mma_f16(acc[mt][nt2 * 2 + 1], af[mt], &bf[nt2][2]);
                }
        }
    }

    #pragma unroll
    for (int nt = 0; nt < 4; nt++) {
        int col = col0 + warpN * 32 + nt * 8 + 2 * t;
        float2 bv = make_float2(0.f, 0.f);
        if (bias) bv = *(const float2*)(bias + col);
        #pragma unroll
        for (int mt = 0; mt < 2; mt++) {
            int row = row0 + warpM * 32 + mt * 16 + g;
            #pragma unroll
            for (int half_ = 0; half_ < 2; half_++) {
                int r = row + half_ * 8;
                float2 v;
                v.x = acc[mt][nt][half_ * 2 + 0] + bv.x;
                v.y = acc[mt][nt][half_ * 2 + 1] + bv.y;
                if (MODE == 1) {
                    float2 rv = *(const float2*)(res + (size_t)r * N + col);
                    v.x += rv.x; v.y += rv.y;
                }
                if (MODE == 2) { v.x = gelu_exact(v.x); v.y = gelu_exact(v.y); }
                if (HOUT) {
                    *reinterpret_cast<__half2*>((__half*)Cv + (size_t)r * N + col) =
                        __floats2half2_rn(v.x, v.y);
                } else {
                    *(float2*)((float*)Cv + (size_t)r * N + col) = v;
                }
            }
        }
    }
}

// ---------------- patchify (im2col gather -> fp16) ----------------
__global__ void patchify_kernel(const float* __restrict__ img) {
    int idx = blockIdx.x * 256 + threadIdx.x;
    if (idx >= B_ * NP_ * D_) return;
    int k = idx % D_;
    int bp = idx / D_;
    int p = bp % NP_;
    int b = bp / NP_;
    int c = k >> 8;
    int rem = k & 255;
    int dy = rem >> 4, dx = rem & 15;
    int y = (p / 14) * P_ + dy;
    int x = (p % 14) * P_ + dx;
    g_patch[idx] = __float2half(img[(((size_t)b * 3 + c) * IMG_ + y) * IMG_ + x]);
}

// ---------------- reductions ----------------
__device__ __forceinline__ void block_sum2(float& a, float& b, float* sm) {
    #pragma unroll
    for (int o = 16; o; o >>= 1) {
        a += __shfl_xor_sync(0xffffffffu, a, o);
        b += __shfl_xor_sync(0xffffffffu, b, o);
    }
    int warp = threadIdx.x >> 5, lane = threadIdx.x & 31;
    int nw = blockDim.x >> 5;
    if (lane == 0) { sm[warp] = a; sm[warp + 8] = b; }
    __syncthreads();
    if (threadIdx.x == 0) {
        float sa = 0.f, sb = 0.f;
        for (int i = 0; i < nw; i++) { sa += sm[i]; sb += sm[i + 8]; }
        sm[0] = sa; sm[8] = sb;
    }
    __syncthreads();
    a = sm[0]; b = sm[8];
    __syncthreads();
}
__device__ __forceinline__ float block_sum(float v, float* sm) {
    #pragma unroll
    for (int o = 16; o; o >>= 1) v += __shfl_xor_sync(0xffffffffu, v, o);
    int warp = threadIdx.x >> 5, lane = threadIdx.x & 31;
    int nw = blockDim.x >> 5;
    if (lane == 0) sm[warp] = v;
    __syncthreads();
    if (threadIdx.x == 0) {
        float s = 0.f;
        for (int i = 0; i < nw; i++) s += sm[i];
        sm[0] = s;
    }
    __syncthreads();
    v = sm[0];
    __syncthreads();
    return v;
}

// ---------------- embed + ln_pre (conv output read from g_ff-as-f32) --------
__global__ void __launch_bounds__(256) embed_ln_kernel(
    const float* __restrict__ cls_emb, const float* __restrict__ pos_emb,
    const float* __restrict__ w, const float* __restrict__ bb)
{
    __shared__ float sm[16];
    const float* conv = (const float*)g_ff;
    int row = blockIdx.x;
    int b = row / SEQ_, s = row % SEQ_;
    int tid = threadIdx.x;
    float v[3];
    #pragma unroll
    for (int i = 0; i < 3; i++) {
        int d = tid + i * 256;
        float base = (s == 0) ? cls_emb[d]
                              : conv[((size_t)(b * NP_ + (s - 1))) * D_ + d];
        v[i] = base + pos_emb[(size_t)s * D_ + d];
    }
    float sum = v[0] + v[1] + v[2];
    float sq = v[0] * v[0] + v[1] * v[1] + v[2] * v[2];
    block_sum2(sum, sq, sm);
    float mean = sum * (1.0f / D_);
    float var = sq * (1.0f / D_) - mean * mean;
    float r = rsqrtf(var + 1e-5f);
    #pragma unroll
    for (int i = 0; i < 3; i++) {
        int d = tid + i * 256;
        g_x[(size_t)row * D_ + d] = (v[i] - mean) * r * w[d] + bb[d];
    }
}

// ---------------- layernorm v2: warp per row, 8 rows per block --------------
__global__ void __launch_bounds__(256) ln_kernel(
    const float* __restrict__ x, __half* __restrict__ y,
    const float* __restrict__ w, const float* __restrict__ bb)
{
    int row = blockIdx.x * 8 + (threadIdx.x >> 5);
    int lane = threadIdx.x & 31;
    const float4* xr = (const float4*)(x + (size_t)row * D_);
    float4 v[6];
    float sum = 0.f, sq = 0.f;
    #pragma unroll
    for (int j = 0; j < 6; j++) {
        v[j] = xr[lane + j * 32];
        sum += v[j].x + v[j].y + v[j].z + v[j].w;
        sq += v[j].x * v[j].x + v[j].y * v[j].y + v[j].z * v[j].z + v[j].w * v[j].w;
    }
    #pragma unroll
    for (int o = 16; o; o >>= 1) {
        sum += __shfl_xor_sync(0xffffffffu, sum, o);
        sq  += __shfl_xor_sync(0xffffffffu, sq, o);
    }
    float mean = sum * (1.0f / D_);
    float var = sq * (1.0f / D_) - mean * mean;
    float r = rsqrtf(var + 1e-5f);
    __half2* yr = (__half2*)(y + (size_t)row * D_);
    const float4* w4 = (const float4*)w;
    const float4* b4 = (const float4*)bb;
    #pragma unroll
    for (int j = 0; j < 6; j++) {
        int idx = lane + j * 32;
        float4 wv = w4[idx], bv = b4[idx];
        float o0 = (v[j].x - mean) * r * wv.x + bv.x;
        float o1 = (v[j].y - mean) * r * wv.y + bv.y;
        float o2 = (v[j].z - mean) * r * wv.z + bv.z;
        float o3 = (v[j].w - mean) * r * wv.w + bv.w;
        yr[idx * 2]     = __floats2half2_rn(o0, o1);
        yr[idx * 2 + 1] = __floats2half2_rn(o2, o3);
    }
}

// ---------------- tensor-core attention ----------------
#define TQA   64
#define SKP   208
#define NTS   26
#define AQOFF 0u
#define AKOFF 8192u
#define APOFF 0u
#define AVOFF 32768u
#define ASMEM_BYTES 65536

__global__ void __launch_bounds__(128) attn3_kernel() {
    extern __shared__ char asmem[];
    uint32_t sb = smem_u32(asmem);
    int tid = threadIdx.x, wid = tid >> 5, lane = tid & 31;
    int g = lane >> 2, t = lane & 3;
    int q0 = blockIdx.x * TQA;
    int bh = blockIdx.y;
    int b = bh / H_, h = bh % H_;
    const __half* qkvb = g_qkv + (size_t)(b * SEQ_) * (3 * D_) + h * HD_;

    __half2 sc2 = __floats2half2_rn(0.125f, 0.125f);
    for (int i = tid; i < TQA * 8; i += 128) {
        int r = i >> 3, c = i & 7;
        uint4 u = make_uint4(0, 0, 0, 0);
        if (q0 + r < SEQ_)
            u = *(const uint4*)(qkvb + (size_t)(q0 + r) * (3 * D_) + c * 8);
        __half2* hp = (__half2*)&u;
        hp[0] = __hmul2(hp[0], sc2); hp[1] = __hmul2(hp[1], sc2);
        hp[2] = __hmul2(hp[2], sc2); hp[3] = __hmul2(hp[3], sc2);
        *(uint4*)(asmem + AQOFF + r * 128 + ((c ^ (r & 7)) * 16)) = u;
    }
    for (int i = tid; i < SKP * 8; i += 128) {
        int r = i >> 3, c = i & 7;
        uint4 u = make_uint4(0, 0, 0, 0);
        if (r < SEQ_)
            u = *(const uint4*)(qkvb + D_ + (size_t)r * (3 * D_) + c * 8);
        *(uint4*)(asmem + AKOFF + r * 128 + ((c ^ (r & 7)) * 16)) = u;
    }
    __syncthreads();

    int ar = lane & 15;
    int asel = lane >> 4;
    int brr = (lane & 7) + ((lane >> 4) << 3);
    int bsel = (lane >> 3) & 1;
    int l7 = lane & 7;

    uint32_t qf[4][4];
    #pragma unroll
    for (int kc = 0; kc < 4; kc++) {
        uint32_t c = kc * 2 + asel;
        LDSM4(qf[kc], sb + AQOFF + (uint32_t)((wid * 16 + ar) * 128) + ((c ^ l7) & 7) * 16);
    }
    float sacc[NTS][4];
    #pragma unroll
    for (int nt = 0; nt < NTS; nt++)
        #pragma unroll
        for (int r = 0; r < 4; r++) sacc[nt][r] = 0.f;

    #pragma unroll
    for (int kc = 0; kc < 4; kc++) {
        uint32_t cb = kc * 2 + bsel;
        uint32_t cboff = ((cb ^ l7) & 7) * 16;
        #pragma unroll
        for (int n16 = 0; n16 < 13; n16++) {
            uint32_t bf[4];
            LDSM4(bf, sb + AKOFF + (uint32_t)((n16 * 16 + brr) * 128) + cboff);
            mma_f16(sacc[n16 * 2],     qf[kc], &bf[0]);
            mma_f16(sacc[n16 * 2 + 1], qf[kc], &bf[2]);
        }
    }

    float mx0 = -1e30f, mx1 = -1e30f;
    #pragma unroll
    for (int nt = 0; nt < NTS; nt++) {
        int c0 = nt * 8 + 2 * t;
        if (c0 >= SEQ_)     { sacc[nt][0] = -1e30f; sacc[nt][2] = -1e30f; }
        if (c0 + 1 >= SEQ_) { sacc[nt][1] = -1e30f; sacc[nt][3] = -1e30f; }
        mx0 = fmaxf(mx0, fmaxf(sacc[nt][0], sacc[nt][1]));
        mx1 = fmaxf(mx1, fmaxf(sacc[nt][2], sacc[nt][3]));
    }
    mx0 = fmaxf(mx0, __shfl_xor_sync(0xffffffffu, mx0, 1));
    mx0 = fmaxf(mx0, __shfl_xor_sync(0xffffffffu, mx0, 2));
    mx1 = fmaxf(mx1, __shfl_xor_sync(0xffffffffu, mx1, 1));
    mx1 = fmaxf(mx1, __shfl_xor_sync(0xffffffffu, mx1, 2));
    float s0 = 0.f, s1 = 0.f;
    #pragma unroll
    for (int nt = 0; nt < NTS; nt++) {
        sacc[nt][0] = expf(sacc[nt][0] - mx0); s0 += sacc[nt][0];
        sacc[nt][1] = expf(sacc[nt][1] - mx0); s0 += sacc[nt][1];
        sacc[nt][2] = expf(sacc[nt][2] - mx1); s1 += sacc[nt][2];
        sacc[nt][3] = expf(sacc[nt][3] - mx1); s1 += sacc[nt][3];
    }
    s0 += __shfl_xor_sync(0xffffffffu, s0, 1);
    s0 += __shfl_xor_sync(0xffffffffu, s0, 2);
    s1 += __shfl_xor_sync(0xffffffffu, s1, 1);
    s1 += __shfl_xor_sync(0xffffffffu, s1, 2);
    float inv0 = 1.0f / s0, inv1 = 1.0f / s1;

    __syncthreads();

    {
        int row0 = wid * 16 + g;
        #pragma unroll
        for (int nt = 0; nt < NTS; nt++) {
            uint32_t sw = (uint32_t)((nt & 24) | ((nt ^ g) & 7));
            *(__half2*)(asmem + APOFF + row0 * 512 + sw * 16 + t * 4) =
                __floats2half2_rn(sacc[nt][0] * inv0, sacc[nt][1] * inv0);
            *(__half2*)(asmem + APOFF + (row0 + 8) * 512 + sw * 16 + t * 4) =
                __floats2half2_rn(sacc[nt][2] * inv1, sacc[nt][3] * inv1);
        }
    }
    for (int rp = tid; rp * 2 < SKP; rp += 128) {
        int r0v = rp * 2, r1v = rp * 2 + 1;
        uint4 u0[8], u1[8];
        if (r0v < SEQ_) {
            const uint4* vp = (const uint4*)(qkvb + 2 * D_ + (size_t)r0v * (3 * D_));
            #pragma unroll
            for (int j = 0; j < 8; j++) u0[j] = vp[j];
        } else {
            #pragma unroll
            for (int j = 0; j < 8; j++) u0[j] = make_uint4(0, 0, 0, 0);
        }
        if (r1v < SEQ_) {
            const uint4* vp = (const uint4*)(qkvb + 2 * D_ + (size_t)r1v * (3 * D_));
            #pragma unroll
            for (int j = 0; j < 8; j++) u1[j] = vp[j];
        } else {
            #pragma unroll
            for (int j = 0; j < 8; j++) u1[j] = make_uint4(0, 0, 0, 0);
        }
        const __half* h0 = (const __half*)u0;
        const __half* h1 = (const __half*)u1;
        int cchunk = r0v >> 3, rin = r0v & 7;
        #pragma unroll
        for (int hd = 0; hd < 64; hd++) {
            uint32_t sw = (uint32_t)((cchunk & 24) | ((cchunk ^ (hd & 7)) & 7));
            *(__half2*)(asmem + AVOFF + hd * 512 + sw * 16 + rin * 2) =
                __halves2half2(h0[hd], h1[hd]);
        }
    }
    __syncthreads();

    float oacc[8][4];
    #pragma unroll
    for (int i = 0; i < 8; i++)
        #pragma unroll
        for (int r = 0; r < 4; r++) oacc[i][r] = 0.f;

    uint32_t aRowP = (uint32_t)((wid * 16 + ar) * 512);
    #pragma unroll
    for (int kc = 0; kc < 13; kc++) {
        uint32_t ca = (uint32_t)(kc * 2 + asel);
        uint32_t pf[4];
        LDSM4(pf, sb + APOFF + aRowP + ((ca & 24) | ((ca ^ (uint32_t)l7) & 7)) * 16);
        uint32_t cb = (uint32_t)(kc * 2 + bsel);
        uint32_t cboff = ((cb & 24) | ((cb ^ (uint32_t)l7) & 7)) * 16;
        #pragma unroll
        for (int n16 = 0; n16 < 4; n16++) {
            uint32_t vf[4];
            LDSM4(vf, sb + AVOFF + (uint32_t)((n16 * 16 + brr) * 512) + cboff);
            mma_f16(oacc[n16 * 2],     pf, &vf[0]);
            mma_f16(oacc[n16 * 2 + 1], pf, &vf[2]);
        }
    }

    #pragma unroll
    for (int nt = 0; nt < 8; nt++) {
        int col = h * HD_ + nt * 8 + 2 * t;
        int r0 = q0 + wid * 16 + g;
        if (r0 < SEQ_)
            *(__half2*)(g_att + (size_t)(b * SEQ_ + r0) * D_ + col) =
                __floats2half2_rn(oacc[nt][0], oacc[nt][1]);
        int r1 = r0 + 8;
        if (r1 < SEQ_)
            *(__half2*)(g_att + (size_t)(b * SEQ_ + r1) * D_ + col) =
                __floats2half2_rn(oacc[nt][2], oacc[nt][3]);
    }
}

// ---------------- final head ----------------
__global__ void __launch_bounds__(256) head_kernel(
    const float* __restrict__ w, const float* __restrict__ bb,
    const float* __restrict__ proj, float* __restrict__ out)
{
    __shared__ float cls[D_];
    __shared__ float feats[E_];
    __shared__ float sm[16];
    int b = blockIdx.x;
    int tid = threadIdx.x;
    const float* xr = g_x + (size_t)(b * SEQ_) * D_;
    float v[3];
    #pragma unroll
    for (int i = 0; i < 3; i++) v[i] = xr[tid + i * 256];
    float sum = v[0] + v[1] + v[2];
    float sq = v[0] * v[0] + v[1] * v[1] + v[2] * v[2];
    block_sum2(sum, sq, sm);
    float mean = sum * (1.0f / D_);
    float var = sq * (1.0f / D_) - mean * mean;
    float r = rsqrtf(var + 1e-5f);
    #pragma unroll
    for (int i = 0; i < 3; i++) {
        int d = tid + i * 256;
        cls[d] = (v[i] - mean) * r * w[d] + bb[d];
    }
    __syncthreads();
    for (int e = tid; e < E_; e += 256) {
        float a = 0.f;
        for (int d = 0; d < D_; d++) a += cls[d] * proj[(size_t)d * E_ + e];
        feats[e] = a;
    }
    __syncthreads();
    float nrm = 0.f;
    for (int e = tid; e < E_; e += 256) nrm += feats[e] * feats[e];
    nrm = block_sum(nrm, sm);
    float rn = rsqrtf(nrm);
    for (int e = tid; e < E_; e += 256) out[(size_t)b * E_ + e] = feats[e] * rn;
}

// ---------------- host ----------------
extern "C" void kernel_launch(void* const* d_in, const int* in_sizes, int n_in,
                              void* d_out, int out_size)
{
    const float* image     = (const float*)d_in[0];
    const float* conv_w    = (const float*)d_in[1];
    const float* cls_emb   = (const float*)d_in[2];
    const float* pos_emb   = (const float*)d_in[3];
    const float* ln_pre_w  = (const float*)d_in[4];
    const float* ln_pre_b  = (const float*)d_in[5];
    const float* ln1_w     = (const float*)d_in[6];
    const float* ln1_b     = (const float*)d_in[7];
    const float* qkv_w     = (const float*)d_in[8];
    const float* qkv_b     = (const float*)d_in[9];
    const float* out_w     = (const float*)d_in[10];
    const float* out_b     = (const float*)d_in[11];
    const float* ln2_w     = (const float*)d_in[12];
    const float* ln2_b     = (const float*)d_in[13];
    const float* fc_w      = (const float*)d_in[14];
    const float* fc_b      = (const float*)d_in[15];
    const float* pr_w      = (const float*)d_in[16];
    const float* pr_b      = (const float*)d_in[17];
    const float* ln_post_w = (const float*)d_in[18];
    const float* ln_post_b = (const float*)d_in[19];
    const float* proj      = (const float*)d_in[20];
    float* out = (float*)d_out;
    (void)in_sizes; (void)n_in; (void)out_size;

    __half *p_patch, *p_ln, *p_att, *p_ff, *p_qkv;
    float  *p_x;
    __half *pw_qkv, *pw_out, *pw_fc, *pw_pr, *pw_conv;
    cudaGetSymbolAddress((void**)&p_patch, g_patch);
    cudaGetSymbolAddress((void**)&p_x,     g_x);
    cudaGetSymbolAddress((void**)&p_ln,    g_ln);
    cudaGetSymbolAddress((void**)&p_qkv,   g_qkv);
    cudaGetSymbolAddress((void**)&p_att,   g_att);
    cudaGetSymbolAddress((void**)&p_ff,    g_ff);
    cudaGetSymbolAddress((void**)&pw_qkv,  w_qkv);
    cudaGetSymbolAddress((void**)&pw_out,  w_out);
    cudaGetSymbolAddress((void**)&pw_fc,   w_fc);
    cudaGetSymbolAddress((void**)&pw_pr,   w_pr);
    cudaGetSymbolAddress((void**)&pw_conv, w_conv);
    float* p_conv = (float*)p_ff;   // f32 conv scratch aliases g_ff

    cudaFuncSetAttribute(gemm_tc<0, false>, cudaFuncAttributeMaxDynamicSharedMemorySize, GSMEM_BYTES);
    cudaFuncSetAttribute(gemm_tc<0, true>,  cudaFuncAttributeMaxDynamicSharedMemorySize, GSMEM_BYTES);
    cudaFuncSetAttribute(gemm_tc<2, true>,  cudaFuncAttributeMaxDynamicSharedMemorySize, GSMEM_BYTES);
    cudaFuncSetAttribute(gemm64<1, false>,  cudaFuncAttributeMaxDynamicSharedMemorySize, GSMEM64);
    cudaFuncSetAttribute(attn3_kernel, cudaFuncAttributeMaxDynamicSharedMemorySize, ASMEM_BYTES);

    auto cvt = [&](const float* s, __half* d, int n) {
        f2h_kernel<<<(n / 8 + 255) / 256, 256>>>((const float4*)s, d, n / 8);
    };
    cvt(qkv_w, pw_qkv, L_ * 3 * D_ * D_);
    cvt(out_w, pw_out, L_ * D_ * D_);
    cvt(fc_w,  pw_fc,  L_ * FF_ * D_);
    cvt(pr_w,  pw_pr,  L_ * D_ * FF_);
    cvt(conv_w, pw_conv, D_ * D_);

    const int MT = MP_ / 128;    // 50
    const int MT64 = MP_ / 64;   // 100
    const int LNB = NTOK / 8;    // 788

    patchify_kernel<<<(B_ * NP_ * D_ + 255) / 256, 256>>>(image);
    gemm_tc<0, false><<<dim3(MT, D_ / 128), 256, GSMEM_BYTES>>>(
        p_patch, pw_conv, nullptr, nullptr, p_conv, D_, D_);
    embed_ln_kernel<<<NTOK, 256>>>(cls_emb, pos_emb, ln_pre_w, ln_pre_b);

    for (int l = 0; l < L_; l++) {
        ln_kernel<<<LNB, 256>>>(p_x, p_ln, ln1_w + l * D_, ln1_b + l * D_);
        gemm_tc<0, true><<<dim3(MT, 3 * D_ / 128), 256, GSMEM_BYTES>>>(
            p_ln, pw_qkv + (size_t)l * 3 * D_ * D_, qkv_b + (size_t)l * 3 * D_,
            nullptr, p_qkv, 3 * D_, D_);
        attn3_kernel<<<dim3((SEQ_ + TQA - 1) / TQA, B_ * H_), 128, ASMEM_BYTES>>>();
        gemm64<1, false><<<dim3(MT64, D_ / 128), 256, GSMEM64>>>(
            p_att, pw_out + (size_t)l * D_ * D_, out_b + (size_t)l * D_,
            p_x, p_x, D_, D_);
        ln_kernel<<<LNB, 256>>>(p_x, p_ln, ln2_w + l * D_, ln2_b + l * D_);
        gemm_tc<2, true><<<dim3(MT, FF_ / 128), 256, GSMEM_BYTES>>>(
            p_ln, pw_fc + (size_t)l * FF_ * D_, fc_b + (size_t)l * FF_,
            nullptr, p_ff, FF_, D_);
        gemm64<1, false><<<dim3(MT64, D_ / 128), 256, GSMEM64>>>(
            p_ff, pw_pr + (size_t)l * D_ * FF_, pr_b + (size_t)l * D_,
            p_x, p_x, D_, FF_);
    }
    head_kernel<<<B_, 256>>>(ln_post_w, ln_post_b, proj, out);
}

// round 16
// speedup vs baseline: 1.0229x; 1.0028x over previous
#include <cuda_runtime.h>
#include <cuda_fp16.h>
#include <math.h>
#include <stdint.h>

// ---------------- problem constants ----------------
#define D_    768
#define H_    12
#define HD_   64
#define FF_   3072
#define SEQ_  197
#define B_    32
#define NTOK  (B_ * SEQ_)     // 6304
#define MP_   6400            // padded token rows (50 * 128)
#define L_    12
#define E_    512
#define NP_   196
#define IMG_  224
#define P_    16

// ---------------- device scratch (no allocation allowed) ----------------
__device__ __half g_patch[MP_ * D_];
__device__ float  g_x[MP_ * D_];
__device__ __half g_ln[MP_ * D_];
__device__ __half g_qkv[MP_ * 3 * D_];
__device__ __half g_att[MP_ * D_];
__device__ __half g_ff[MP_ * FF_];        // MLP hidden; also f32 conv scratch
// fp16 weight copies
__device__ __half w_qkv[L_ * 3 * D_ * D_];
__device__ __half w_out[L_ * D_ * D_];
__device__ __half w_fc[L_ * FF_ * D_];
__device__ __half w_pr[L_ * D_ * FF_];
__device__ __half w_conv[D_ * D_];

// ---------------- helpers ----------------
__device__ __forceinline__ float gelu_exact(float v) {
    return 0.5f * v * (1.0f + erff(v * 0.70710678118654752f));
}
#define CP_ASYNC16(dst, src) \
    asm volatile("cp.async.cg.shared.global [%0], [%1], 16;\n" :: "r"(dst), "l"(src))
#define CP_COMMIT() asm volatile("cp.async.commit_group;\n" ::: "memory")
#define CP_WAIT1()  asm volatile("cp.async.wait_group 1;\n" ::: "memory")

__device__ __forceinline__ uint32_t smem_u32(const void* p) {
    uint32_t a;
    asm("{ .reg .u64 t; cvta.to.shared.u64 t, %1; cvt.u32.u64 %0, t; }" : "=r"(a) : "l"(p));
    return a;
}
__device__ __forceinline__ void mma_f16(float* c, const uint32_t* a, const uint32_t* b) {
    asm volatile(
        "mma.sync.aligned.m16n8k16.row.col.f32.f16.f16.f32 "
        "{%0,%1,%2,%3}, {%4,%5,%6,%7}, {%8,%9}, {%0,%1,%2,%3};"
        : "+f"(c[0]), "+f"(c[1]), "+f"(c[2]), "+f"(c[3])
        : "r"(a[0]), "r"(a[1]), "r"(a[2]), "r"(a[3]), "r"(b[0]), "r"(b[1]));
}
#define LDSM4(r, a) \
    asm volatile("ldmatrix.sync.aligned.m8n8.x4.shared.b16 {%0,%1,%2,%3}, [%4];" \
        : "=r"((r)[0]), "=r"((r)[1]), "=r"((r)[2]), "=r"((r)[3]) : "r"(a))

__device__ __forceinline__ uint32_t h2_u32(__half2 h) {
    return *reinterpret_cast<uint32_t*>(&h);
}

// ---------------- fused f32 -> f16 weight conversion (all 5 tensors) -------
#define NW1 (L_ * 3 * D_ * D_)               // qkv 21233664
#define NW2 (NW1 + L_ * D_ * D_)             // +out 28311552
#define NW3 (NW2 + L_ * FF_ * D_)            // +fc  56623104
#define NW4 (NW3 + L_ * D_ * FF_)            // +pr  84934656
#define NW5 (NW4 + D_ * D_)                  // +conv 85524480
#define NCHUNK (NW5 / 8)                     // 10690560

__global__ void f2h_all_kernel(
    const float* __restrict__ s_qkv, const float* __restrict__ s_out,
    const float* __restrict__ s_fc,  const float* __restrict__ s_pr,
    const float* __restrict__ s_conv)
{
    int i = blockIdx.x * 256 + threadIdx.x;
    if (i >= NCHUNK) return;
    size_t e = (size_t)i * 8;
    const float* src;
    __half* dst;
    if (e < NW1)      { src = s_qkv  + e;         dst = w_qkv  + e; }
    else if (e < NW2) { src = s_out  + (e - NW1); dst = w_out  + (e - NW1); }
    else if (e < NW3) { src = s_fc   + (e - NW2); dst = w_fc   + (e - NW2); }
    else if (e < NW4) { src = s_pr   + (e - NW3); dst = w_pr   + (e - NW3); }
    else              { src = s_conv + (e - NW4); dst = w_conv + (e - NW4); }
    float4 a = *(const float4*)src;
    float4 b = *(const float4*)(src + 4);
    uint4 u;
    u.x = h2_u32(__floats2half2_rn(a.x, a.y));
    u.y = h2_u32(__floats2half2_rn(a.z, a.w));
    u.z = h2_u32(__floats2half2_rn(b.x, b.y));
    u.w = h2_u32(__floats2half2_rn(b.z, b.w));
    *reinterpret_cast<uint4*>(dst) = u;
}

// ---------------- fp16 tensor-core GEMM: C = A[M,K] * W[N,K]^T ----------------
// block tile 128x128x64, 8 warps (4x2), warp tile 32x64, m16n8k16 f16 MMA
// 3-stage cp.async pipeline (32KB/stage -> 2 CTAs per SM), XOR-swizzled smem
#define STAGE_BYTES 32768u
#define GSMEM_BYTES (3 * 32768)

template <int MODE, bool HOUT>
__global__ void __launch_bounds__(256, 2) gemm_tc(
    const __half* __restrict__ A, const __half* __restrict__ W,
    const float* __restrict__ bias, const float* __restrict__ res,
    void* __restrict__ Cv, int N, int K)
{
    extern __shared__ float smem[];
    uint32_t sbase = smem_u32(smem);
    int tid = threadIdx.x;
    int wid = tid >> 5, lane = tid & 31;
    int g = lane >> 2, t = lane & 3;
    int warpM = wid & 3, warpN = wid >> 2;

    int row0 = blockIdx.x * 128;
    int col0 = blockIdx.y * 128;
    const __half* Abase = A + (size_t)row0 * K;
    const __half* Wbase = W + (size_t)col0 * K;

    auto load_stage = [&](int s, int k0) {
        uint32_t ab = sbase + (uint32_t)s * STAGE_BYTES;
        uint32_t bb = ab + 16384u;
        #pragma unroll
        for (int i = 0; i < 4; i++) {
            int idx = tid + i * 256;
            int r = idx >> 3, c = idx & 7;
            uint32_t d = ab + (uint32_t)(r * 128 + ((c ^ (r & 7)) * 16));
            CP_ASYNC16(d, Abase + (size_t)r * K + k0 + c * 8);
        }
        #pragma unroll
        for (int i = 0; i < 4; i++) {
            int idx = tid + i * 256;
            int r = idx >> 3, c = idx & 7;
            uint32_t d = bb + (uint32_t)(r * 128 + ((c ^ (r & 7)) * 16));
            CP_ASYNC16(d, Wbase + (size_t)r * K + k0 + c * 8);
        }
        CP_COMMIT();
    };

    float acc[2][8][4];
    #pragma unroll
    for (int i = 0; i < 2; i++)
        #pragma unroll
        for (int j = 0; j < 8; j++)
            #pragma unroll
            for (int r = 0; r < 4; r++) acc[i][j][r] = 0.f;

    int ar = lane & 15;
    int asel = lane >> 4;
    int brr = (lane & 7) + ((lane >> 4) << 3);
    int bsel = (lane >> 3) & 1;
    uint32_t aRow[2], bRow[4], aChunk[4], bChunk[4];
    #pragma unroll
    for (int mt = 0; mt < 2; mt++)
        aRow[mt] = (uint32_t)((warpM * 32 + mt * 16 + ar) * 128);
    #pragma unroll
    for (int nt2 = 0; nt2 < 4; nt2++)
        bRow[nt2] = (uint32_t)((warpN * 64 + nt2 * 16 + brr) * 128);
    #pragma unroll
    for (int kt = 0; kt < 4; kt++) {
        aChunk[kt] = (uint32_t)((((kt * 2 + asel) ^ (lane & 7)) * 16));
        bChunk[kt] = (uint32_t)((((kt * 2 + bsel) ^ (lane & 7)) * 16));
    }

    int nIter = K >> 6;
    load_stage(0, 0);
    load_stage(1, 64);

    for (int it = 0; it < nIter; it++) {
        CP_WAIT1();
        __syncthreads();
        if (it + 2 < nIter) load_stage((it + 2) % 3, (it + 2) * 64);
        else CP_COMMIT();

        uint32_t ab = sbase + (uint32_t)(it % 3) * STAGE_BYTES;
        uint32_t bb = ab + 16384u;
        #pragma unroll
        for (int kt = 0; kt < 4; kt++) {
            uint32_t af[2][4], bf[4][4];
            #pragma unroll
            for (int mt = 0; mt < 2; mt++)
                LDSM4(af[mt], ab + aRow[mt] + aChunk[kt]);
            #pragma unroll
            for (int nt2 = 0; nt2 < 4; nt2++)
                LDSM4(bf[nt2], bb + bRow[nt2] + bChunk[kt]);
            #pragma unroll
            for (int mt = 0; mt < 2; mt++)
                #pragma unroll
                for (int nt2 = 0; nt2 < 4; nt2++) {
                    mma_f16(acc[mt][nt2 * 2],     af[mt], &bf[nt2][0]);
                    mma_f16(acc[mt][nt2 * 2 + 1], af[mt], &bf[nt2][2]);
                }
        }
    }

    #pragma unroll
    for (int nt = 0; nt < 8; nt++) {
        int col = col0 + warpN * 64 + nt * 8 + 2 * t;
        float2 bv = make_float2(0.f, 0.f);
        if (bias) bv = *(const float2*)(bias + col);
        #pragma unroll
        for (int mt = 0; mt < 2; mt++) {
            int row = row0 + warpM * 32 + mt * 16 + g;
            #pragma unroll
            for (int half_ = 0; half_ < 2; half_++) {
                int r = row + half_ * 8;
                float2 v;
                v.x = acc[mt][nt][half_ * 2 + 0] + bv.x;
                v.y = acc[mt][nt][half_ * 2 + 1] + bv.y;
                if (MODE == 1) {
                    float2 rv = *(const float2*)(res + (size_t)r * N + col);
                    v.x += rv.x; v.y += rv.y;
                }
                if (MODE == 2) { v.x = gelu_exact(v.x); v.y = gelu_exact(v.y); }
                if (HOUT) {
                    *reinterpret_cast<__half2*>((__half*)Cv + (size_t)r * N + col) =
                        __floats2half2_rn(v.x, v.y);
                } else {
                    *(float2*)((float*)Cv + (size_t)r * N + col) = v;
                }
            }
        }
    }
}

// ---------------- 64x128 tile variant (wave-friendly, for out/pr) -----------
#define STAGE64 24576u
#define GSMEM64 (3 * 24576)

template <int MODE, bool HOUT>
__global__ void __launch_bounds__(256, 2) gemm64(
    const __half* __restrict__ A, const __half* __restrict__ W,
    const float* __restrict__ bias, const float* __restrict__ res,
    void* __restrict__ Cv, int N, int K)
{
    extern __shared__ float smem[];
    uint32_t sbase = smem_u32(smem);
    int tid = threadIdx.x;
    int wid = tid >> 5, lane = tid & 31;
    int g = lane >> 2, t = lane & 3;
    int warpM = wid & 1, warpN = wid >> 1;       // 2 x 4 warp grid

    int row0 = blockIdx.x * 64;
    int col0 = blockIdx.y * 128;
    const __half* Abase = A + (size_t)row0 * K;
    const __half* Wbase = W + (size_t)col0 * K;

    auto load_stage = [&](int s, int k0) {
        uint32_t ab = sbase + (uint32_t)s * STAGE64;
        uint32_t bb = ab + 8192u;
        #pragma unroll
        for (int i = 0; i < 2; i++) {
            int idx = tid + i * 256;
            int r = idx >> 3, c = idx & 7;
            uint32_t d = ab + (uint32_t)(r * 128 + ((c ^ (r & 7)) * 16));
            CP_ASYNC16(d, Abase + (size_t)r * K + k0 + c * 8);
        }
        #pragma unroll
        for (int i = 0; i < 4; i++) {
            int idx = tid + i * 256;
            int r = idx >> 3, c = idx & 7;
            uint32_t d = bb + (uint32_t)(r * 128 + ((c ^ (r & 7)) * 16));
            CP_ASYNC16(d, Wbase + (size_t)r * K + k0 + c * 8);
        }
        CP_COMMIT();
    };

    float acc[2][4][4];
    #pragma unroll
    for (int i = 0; i < 2; i++)
        #pragma unroll
        for (int j = 0; j < 4; j++)
            #pragma unroll
            for (int r = 0; r < 4; r++) acc[i][j][r] = 0.f;

    int ar = lane & 15;
    int asel = lane >> 4;
    int brr = (lane & 7) + ((lane >> 4) << 3);
    int bsel = (lane >> 3) & 1;
    uint32_t aRow[2], bRow[2], aChunk[4], bChunk[4];
    #pragma unroll
    for (int mt = 0; mt < 2; mt++)
        aRow[mt] = (uint32_t)((warpM * 32 + mt * 16 + ar) * 128);
    #pragma unroll
    for (int nt2 = 0; nt2 < 2; nt2++)
        bRow[nt2] = (uint32_t)((warpN * 32 + nt2 * 16 + brr) * 128);
    #pragma unroll
    for (int kt = 0; kt < 4; kt++) {
        aChunk[kt] = (uint32_t)((((kt * 2 + asel) ^ (lane & 7)) * 16));
        bChunk[kt] = (uint32_t)((((kt * 2 + bsel) ^ (lane & 7)) * 16));
    }

    int nIter = K >> 6;
    load_stage(0, 0);
    load_stage(1, 64);

    for (int it = 0; it < nIter; it++) {
        CP_WAIT1();
        __syncthreads();
        if (it + 2 < nIter) load_stage((it + 2) % 3, (it + 2) * 64);
        else CP_COMMIT();

        uint32_t ab = sbase + (uint32_t)(it % 3) * STAGE64;
        uint32_t bb = ab + 8192u;
        #pragma unroll
        for (int kt = 0; kt < 4; kt++) {
            uint32_t af[2][4], bf[2][4];
            #pragma unroll
            for (int mt = 0; mt < 2; mt++)
                LDSM4(af[mt], ab + aRow[mt] + aChunk[kt]);
            #pragma unroll
            for (int nt2 = 0; nt2 < 2; nt2++)
                LDSM4(bf[nt2], bb + bRow[nt2] + bChunk[kt]);
            #pragma unroll
            for (int mt = 0; mt < 2; mt++)
                #pragma unroll
                for (int nt2 = 0; nt2 < 2; nt2++) {
                    mma_f16(acc[mt][nt2 * 2],     af[mt], &bf[nt2][0]);
                    mma_f16(acc[mt][nt2 * 2 + 1], af[mt], &bf[nt2][2]);
                }
        }
    }

    #pragma unroll
    for (int nt = 0; nt < 4; nt++) {
        int col = col0 + warpN * 32 + nt * 8 + 2 * t;
        float2 bv = make_float2(0.f, 0.f);
        if (bias) bv = *(const float2*)(bias + col);
        #pragma unroll
        for (int mt = 0; mt < 2; mt++) {
            int row = row0 + warpM * 32 + mt * 16 + g;
            #pragma unroll
            for (int half_ = 0; half_ < 2; half_++) {
                int r = row + half_ * 8;
                float2 v;
                v.x = acc[mt][nt][half_ * 2 + 0] + bv.x;
                v.y = acc[mt][nt][half_ * 2 + 1] + bv.y;
                if (MODE == 1) {
                    float2 rv = *(const float2*)(res + (size_t)r * N + col);
                    v.x += rv.x; v.y += rv.y;
                }
                if (MODE == 2) { v.x = gelu_exact(v.x); v.y = gelu_exact(v.y); }
                if (HOUT) {
                    *reinterpret_cast<__half2*>((__half*)Cv + (size_t)r * N + col) =
                        __floats2half2_rn(v.x, v.y);
                } else {
                    *(float2*)((float*)Cv + (size_t)r * N + col) = v;
                }
            }
        }
    }
}

// ---------------- patchify (im2col gather -> fp16) ----------------
__global__ void patchify_kernel(const float* __restrict__ img) {
    int idx = blockIdx.x * 256 + threadIdx.x;
    if (idx >= B_ * NP_ * D_) return;
    int k = idx % D_;
    int bp = idx / D_;
    int p = bp % NP_;
    int b = bp / NP_;
    int c = k >> 8;
    int rem = k & 255;
    int dy = rem >> 4, dx = rem & 15;
    int y = (p / 14) * P_ + dy;
    int x = (p % 14) * P_ + dx;
    g_patch[idx] = __float2half(img[(((size_t)b * 3 + c) * IMG_ + y) * IMG_ + x]);
}

// ---------------- reductions ----------------
__device__ __forceinline__ float block_sum(float v, float* sm) {
    #pragma unroll
    for (int o = 16; o; o >>= 1) v += __shfl_xor_sync(0xffffffffu, v, o);
    int warp = threadIdx.x >> 5, lane = threadIdx.x & 31;
    int nw = blockDim.x >> 5;
    if (lane == 0) sm[warp] = v;
    __syncthreads();
    if (threadIdx.x == 0) {
        float s = 0.f;
        for (int i = 0; i < nw; i++) s += sm[i];
        sm[0] = s;
    }
    __syncthreads();
    v = sm[0];
    __syncthreads();
    return v;
}

// ---------------- embed + ln_pre: warp per row (conv from g_ff-as-f32) ------
__global__ void __launch_bounds__(256) embed_ln_kernel(
    const float* __restrict__ cls_emb, const float* __restrict__ pos_emb,
    const float* __restrict__ w, const float* __restrict__ bb)
{
    const float* conv = (const float*)g_ff;
    int row = blockIdx.x * 8 + (threadIdx.x >> 5);
    int lane = threadIdx.x & 31;
    int b = row / SEQ_, s = row % SEQ_;
    const float4* base4 = (s == 0)
        ? (const float4*)cls_emb
        : (const float4*)(conv + ((size_t)(b * NP_ + (s - 1))) * D_);
    const float4* pos4 = (const float4*)(pos_emb + (size_t)s * D_);
    float4 v[6];
    float sum = 0.f, sq = 0.f;
    #pragma unroll
    for (int j = 0; j < 6; j++) {
        int idx = lane + j * 32;
        float4 a = base4[idx], p = pos4[idx];
        v[j].x = a.x + p.x; v[j].y = a.y + p.y;
        v[j].z = a.z + p.z; v[j].w = a.w + p.w;
        sum += v[j].x + v[j].y + v[j].z + v[j].w;
        sq += v[j].x * v[j].x + v[j].y * v[j].y + v[j].z * v[j].z + v[j].w * v[j].w;
    }
    #pragma unroll
    for (int o = 16; o; o >>= 1) {
        sum += __shfl_xor_sync(0xffffffffu, sum, o);
        sq  += __shfl_xor_sync(0xffffffffu, sq, o);
    }
    float mean = sum * (1.0f / D_);
    float var = sq * (1.0f / D_) - mean * mean;
    float r = rsqrtf(var + 1e-5f);
    float4* yr = (float4*)(g_x + (size_t)row * D_);
    const float4* w4 = (const float4*)w;
    const float4* b4 = (const float4*)bb;
    #pragma unroll
    for (int j = 0; j < 6; j++) {
        int idx = lane + j * 32;
        float4 wv = w4[idx], bv = b4[idx];
        float4 o;
        o.x = (v[j].x - mean) * r * wv.x + bv.x;
        o.y = (v[j].y - mean) * r * wv.y + bv.y;
        o.z = (v[j].z - mean) * r * wv.z + bv.z;
        o.w = (v[j].w - mean) * r * wv.w + bv.w;
        yr[idx] = o;
    }
}

// ---------------- layernorm v2: warp per row, 8 rows per block --------------
__global__ void __launch_bounds__(256) ln_kernel(
    const float* __restrict__ x, __half* __restrict__ y,
    const float* __restrict__ w, const float* __restrict__ bb)
{
    int row = blockIdx.x * 8 + (threadIdx.x >> 5);
    int lane = threadIdx.x & 31;
    const float4* xr = (const float4*)(x + (size_t)row * D_);
    float4 v[6];
    float sum = 0.f, sq = 0.f;
    #pragma unroll
    for (int j = 0; j < 6; j++) {
        v[j] = xr[lane + j * 32];
        sum += v[j].x + v[j].y + v[j].z + v[j].w;
        sq += v[j].x * v[j].x + v[j].y * v[j].y + v[j].z * v[j].z + v[j].w * v[j].w;
    }
    #pragma unroll
    for (int o = 16; o; o >>= 1) {
        sum += __shfl_xor_sync(0xffffffffu, sum, o);
        sq  += __shfl_xor_sync(0xffffffffu, sq, o);
    }
    float mean = sum * (1.0f / D_);
    float var = sq * (1.0f / D_) - mean * mean;
    float r = rsqrtf(var + 1e-5f);
    __half2* yr = (__half2*)(y + (size_t)row * D_);
    const float4* w4 = (const float4*)w;
    const float4* b4 = (const float4*)bb;
    #pragma unroll
    for (int j = 0; j < 6; j++) {
        int idx = lane + j * 32;
        float4 wv = w4[idx], bv = b4[idx];
        float o0 = (v[j].x - mean) * r * wv.x + bv.x;
        float o1 = (v[j].y - mean) * r * wv.y + bv.y;
        float o2 = (v[j].z - mean) * r * wv.z + bv.z;
        float o3 = (v[j].w - mean) * r * wv.w + bv.w;
        yr[idx * 2]     = __floats2half2_rn(o0, o1);
        yr[idx * 2 + 1] = __floats2half2_rn(o2, o3);
    }
}

// ---------------- tensor-core attention ----------------
#define TQA   64
#define SKP   208
#define NTS   26
#define AQOFF 0u
#define AKOFF 8192u
#define APOFF 0u
#define AVOFF 32768u
#define ASMEM_BYTES 65536

__global__ void __launch_bounds__(128) attn3_kernel() {
    extern __shared__ char asmem[];
    uint32_t sb = smem_u32(asmem);
    int tid = threadIdx.x, wid = tid >> 5, lane = tid & 31;
    int g = lane >> 2, t = lane & 3;
    int q0 = blockIdx.x * TQA;
    int bh = blockIdx.y;
    int b = bh / H_, h = bh % H_;
    const __half* qkvb = g_qkv + (size_t)(b * SEQ_) * (3 * D_) + h * HD_;

    __half2 sc2 = __floats2half2_rn(0.125f, 0.125f);
    for (int i = tid; i < TQA * 8; i += 128) {
        int r = i >> 3, c = i & 7;
        uint4 u = make_uint4(0, 0, 0, 0);
        if (q0 + r < SEQ_)
            u = *(const uint4*)(qkvb + (size_t)(q0 + r) * (3 * D_) + c * 8);
        __half2* hp = (__half2*)&u;
        hp[0] = __hmul2(hp[0], sc2); hp[1] = __hmul2(hp[1], sc2);
        hp[2] = __hmul2(hp[2], sc2); hp[3] = __hmul2(hp[3], sc2);
        *(uint4*)(asmem + AQOFF + r * 128 + ((c ^ (r & 7)) * 16)) = u;
    }
    for (int i = tid; i < SKP * 8; i += 128) {
        int r = i >> 3, c = i & 7;
        uint4 u = make_uint4(0, 0, 0, 0);
        if (r < SEQ_)
            u = *(const uint4*)(qkvb + D_ + (size_t)r * (3 * D_) + c * 8);
        *(uint4*)(asmem + AKOFF + r * 128 + ((c ^ (r & 7)) * 16)) = u;
    }
    __syncthreads();

    int ar = lane & 15;
    int asel = lane >> 4;
    int brr = (lane & 7) + ((lane >> 4) << 3);
    int bsel = (lane >> 3) & 1;
    int l7 = lane & 7;

    uint32_t qf[4][4];
    #pragma unroll
    for (int kc = 0; kc < 4; kc++) {
        uint32_t c = kc * 2 + asel;
        LDSM4(qf[kc], sb + AQOFF + (uint32_t)((wid * 16 + ar) * 128) + ((c ^ l7) & 7) * 16);
    }
    float sacc[NTS][4];
    #pragma unroll
    for (int nt = 0; nt < NTS; nt++)
        #pragma unroll
        for (int r = 0; r < 4; r++) sacc[nt][r] = 0.f;

    #pragma unroll
    for (int kc = 0; kc < 4; kc++) {
        uint32_t cb = kc * 2 + bsel;
        uint32_t cboff = ((cb ^ l7) & 7) * 16;
        #pragma unroll
        for (int n16 = 0; n16 < 13; n16++) {
            uint32_t bf[4];
            LDSM4(bf, sb + AKOFF + (uint32_t)((n16 * 16 + brr) * 128) + cboff);
            mma_f16(sacc[n16 * 2],     qf[kc], &bf[0]);
            mma_f16(sacc[n16 * 2 + 1], qf[kc], &bf[2]);
        }
    }

    float mx0 = -1e30f, mx1 = -1e30f;
    #pragma unroll
    for (int nt = 0; nt < NTS; nt++) {
        int c0 = nt * 8 + 2 * t;
        if (c0 >= SEQ_)     { sacc[nt][0] = -1e30f; sacc[nt][2] = -1e30f; }
        if (c0 + 1 >= SEQ_) { sacc[nt][1] = -1e30f; sacc[nt][3] = -1e30f; }
        mx0 = fmaxf(mx0, fmaxf(sacc[nt][0], sacc[nt][1]));
        mx1 = fmaxf(mx1, fmaxf(sacc[nt][2], sacc[nt][3]));
    }
    mx0 = fmaxf(mx0, __shfl_xor_sync(0xffffffffu, mx0, 1));
    mx0 = fmaxf(mx0, __shfl_xor_sync(0xffffffffu, mx0, 2));
    mx1 = fmaxf(mx1, __shfl_xor_sync(0xffffffffu, mx1, 1));
    mx1 = fmaxf(mx1, __shfl_xor_sync(0xffffffffu, mx1, 2));
    float s0 = 0.f, s1 = 0.f;
    #pragma unroll
    for (int nt = 0; nt < NTS; nt++) {
        sacc[nt][0] = expf(sacc[nt][0] - mx0); s0 += sacc[nt][0];
        sacc[nt][1] = expf(sacc[nt][1] - mx0); s0 += sacc[nt][1];
        sacc[nt][2] = expf(sacc[nt][2] - mx1); s1 += sacc[nt][2];
        sacc[nt][3] = expf(sacc[nt][3] - mx1); s1 += sacc[nt][3];
    }
    s0 += __shfl_xor_sync(0xffffffffu, s0, 1);
    s0 += __shfl_xor_sync(0xffffffffu, s0, 2);
    s1 += __shfl_xor_sync(0xffffffffu, s1, 1);
    s1 += __shfl_xor_sync(0xffffffffu, s1, 2);
    float inv0 = 1.0f / s0, inv1 = 1.0f / s1;

    __syncthreads();

    {
        int row0 = wid * 16 + g;
        #pragma unroll
        for (int nt = 0; nt < NTS; nt++) {
            uint32_t sw = (uint32_t)((nt & 24) | ((nt ^ g) & 7));
            *(__half2*)(asmem + APOFF + row0 * 512 + sw * 16 + t * 4) =
                __floats2half2_rn(sacc[nt][0] * inv0, sacc[nt][1] * inv0);
            *(__half2*)(asmem + APOFF + (row0 + 8) * 512 + sw * 16 + t * 4) =
                __floats2half2_rn(sacc[nt][2] * inv1, sacc[nt][3] * inv1);
        }
    }
    for (int rp = tid; rp * 2 < SKP; rp += 128) {
        int r0v = rp * 2, r1v = rp * 2 + 1;
        uint4 u0[8], u1[8];
        if (r0v < SEQ_) {
            const uint4* vp = (const uint4*)(qkvb + 2 * D_ + (size_t)r0v * (3 * D_));
            #pragma unroll
            for (int j = 0; j < 8; j++) u0[j] = vp[j];
        } else {
            #pragma unroll
            for (int j = 0; j < 8; j++) u0[j] = make_uint4(0, 0, 0, 0);
        }
        if (r1v < SEQ_) {
            const uint4* vp = (const uint4*)(qkvb + 2 * D_ + (size_t)r1v * (3 * D_));
            #pragma unroll
            for (int j = 0; j < 8; j++) u1[j] = vp[j];
        } else {
            #pragma unroll
            for (int j = 0; j < 8; j++) u1[j] = make_uint4(0, 0, 0, 0);
        }
        const __half* h0 = (const __half*)u0;
        const __half* h1 = (const __half*)u1;
        int cchunk = r0v >> 3, rin = r0v & 7;
        #pragma unroll
        for (int hd = 0; hd < 64; hd++) {
            uint32_t sw = (uint32_t)((cchunk & 24) | ((cchunk ^ (hd & 7)) & 7));
            *(__half2*)(asmem + AVOFF + hd * 512 + sw * 16 + rin * 2) =
                __halves2half2(h0[hd], h1[hd]);
        }
    }
    __syncthreads();

    float oacc[8][4];
    #pragma unroll
    for (int i = 0; i < 8; i++)
        #pragma unroll
        for (int r = 0; r < 4; r++) oacc[i][r] = 0.f;

    uint32_t aRowP = (uint32_t)((wid * 16 + ar) * 512);
    #pragma unroll
    for (int kc = 0; kc < 13; kc++) {
        uint32_t ca = (uint32_t)(kc * 2 + asel);
        uint32_t pf[4];
        LDSM4(pf, sb + APOFF + aRowP + ((ca & 24) | ((ca ^ (uint32_t)l7) & 7)) * 16);
        uint32_t cb = (uint32_t)(kc * 2 + bsel);
        uint32_t cboff = ((cb & 24) | ((cb ^ (uint32_t)l7) & 7)) * 16;
        #pragma unroll
        for (int n16 = 0; n16 < 4; n16++) {
            uint32_t vf[4];
            LDSM4(vf, sb + AVOFF + (uint32_t)((n16 * 16 + brr) * 512) + cboff);
            mma_f16(oacc[n16 * 2],     pf, &vf[0]);
            mma_f16(oacc[n16 * 2 + 1], pf, &vf[2]);
        }
    }

    #pragma unroll
    for (int nt = 0; nt < 8; nt++) {
        int col = h * HD_ + nt * 8 + 2 * t;
        int r0 = q0 + wid * 16 + g;
        if (r0 < SEQ_)
            *(__half2*)(g_att + (size_t)(b * SEQ_ + r0) * D_ + col) =
                __floats2half2_rn(oacc[nt][0], oacc[nt][1]);
        int r1 = r0 + 8;
        if (r1 < SEQ_)
            *(__half2*)(g_att + (size_t)(b * SEQ_ + r1) * D_ + col) =
                __floats2half2_rn(oacc[nt][2], oacc[nt][3]);
    }
}

// ---------------- final head ----------------
__global__ void __launch_bounds__(256) head_kernel(
    const float* __restrict__ w, const float* __restrict__ bb,
    const float* __restrict__ proj, float* __restrict__ out)
{
    __shared__ float cls[D_];
    __shared__ float feats[E_];
    __shared__ float sm[16];
    int b = blockIdx.x;
    int tid = threadIdx.x;
    const float* xr = g_x + (size_t)(b * SEQ_) * D_;
    float v[3];
    #pragma unroll
    for (int i = 0; i < 3; i++) v[i] = xr[tid + i * 256];
    float sum = v[0] + v[1] + v[2];
    float sq = v[0] * v[0] + v[1] * v[1] + v[2] * v[2];
    sum = block_sum(sum, sm);
    sq = block_sum(sq, sm);
    float mean = sum * (1.0f / D_);
    float var = sq * (1.0f / D_) - mean * mean;
    float r = rsqrtf(var + 1e-5f);
    #pragma unroll
    for (int i = 0; i < 3; i++) {
        int d = tid + i * 256;
        cls[d] = (v[i] - mean) * r * w[d] + bb[d];
    }
    __syncthreads();
    for (int e = tid; e < E_; e += 256) {
        float a = 0.f;
        for (int d = 0; d < D_; d++) a += cls[d] * proj[(size_t)d * E_ + e];
        feats[e] = a;
    }
    __syncthreads();
    float nrm = 0.f;
    for (int e = tid; e < E_; e += 256) nrm += feats[e] * feats[e];
    nrm = block_sum(nrm, sm);
    float rn = rsqrtf(nrm);
    for (int e = tid; e < E_; e += 256) out[(size_t)b * E_ + e] = feats[e] * rn;
}

// ---------------- host ----------------
extern "C" void kernel_launch(void* const* d_in, const int* in_sizes, int n_in,
                              void* d_out, int out_size)
{
    const float* image     = (const float*)d_in[0];
    const float* conv_w    = (const float*)d_in[1];
    const float* cls_emb   = (const float*)d_in[2];
    const float* pos_emb   = (const float*)d_in[3];
    const float* ln_pre_w  = (const float*)d_in[4];
    const float* ln_pre_b  = (const float*)d_in[5];
    const float* ln1_w     = (const float*)d_in[6];
    const float* ln1_b     = (const float*)d_in[7];
    const float* qkv_w     = (const float*)d_in[8];
    const float* qkv_b     = (const float*)d_in[9];
    const float* out_w     = (const float*)d_in[10];
    const float* out_b     = (const float*)d_in[11];
    const float* ln2_w     = (const float*)d_in[12];
    const float* ln2_b     = (const float*)d_in[13];
    const float* fc_w      = (const float*)d_in[14];
    const float* fc_b      = (const float*)d_in[15];
    const float* pr_w      = (const float*)d_in[16];
    const float* pr_b      = (const float*)d_in[17];
    const float* ln_post_w = (const float*)d_in[18];
    const float* ln_post_b = (const float*)d_in[19];
    const float* proj      = (const float*)d_in[20];
    float* out = (float*)d_out;
    (void)in_sizes; (void)n_in; (void)out_size;

    __half *p_patch, *p_ln, *p_att, *p_ff, *p_qkv;
    float  *p_x;
    __half *pw_qkv, *pw_out, *pw_fc, *pw_pr, *pw_conv;
    cudaGetSymbolAddress((void**)&p_patch, g_patch);
    cudaGetSymbolAddress((void**)&p_x,     g_x);
    cudaGetSymbolAddress((void**)&p_ln,    g_ln);
    cudaGetSymbolAddress((void**)&p_qkv,   g_qkv);
    cudaGetSymbolAddress((void**)&p_att,   g_att);
    cudaGetSymbolAddress((void**)&p_ff,    g_ff);
    cudaGetSymbolAddress((void**)&pw_qkv,  w_qkv);
    cudaGetSymbolAddress((void**)&pw_out,  w_out);
    cudaGetSymbolAddress((void**)&pw_fc,   w_fc);
    cudaGetSymbolAddress((void**)&pw_pr,   w_pr);
    cudaGetSymbolAddress((void**)&pw_conv, w_conv);
    float* p_conv = (float*)p_ff;   // f32 conv scratch aliases g_ff

    cudaFuncSetAttribute(gemm_tc<0, false>, cudaFuncAttributeMaxDynamicSharedMemorySize, GSMEM_BYTES);
    cudaFuncSetAttribute(gemm_tc<0, true>,  cudaFuncAttributeMaxDynamicSharedMemorySize, GSMEM_BYTES);
    cudaFuncSetAttribute(gemm_tc<2, true>,  cudaFuncAttributeMaxDynamicSharedMemorySize, GSMEM_BYTES);
    cudaFuncSetAttribute(gemm64<1, false>,  cudaFuncAttributeMaxDynamicSharedMemorySize, GSMEM64);
    cudaFuncSetAttribute(attn3_kernel, cudaFuncAttributeMaxDynamicSharedMemorySize, ASMEM_BYTES);

    // fused single-launch weight conversion
    f2h_all_kernel<<<(NCHUNK + 255) / 256, 256>>>(qkv_w, out_w, fc_w, pr_w, conv_w);

    const int MT = MP_ / 128;    // 50
    const int MT64 = MP_ / 64;   // 100
    const int LNB = NTOK / 8;    // 788

    patchify_kernel<<<(B_ * NP_ * D_ + 255) / 256, 256>>>(image);
    gemm_tc<0, false><<<dim3(MT, D_ / 128), 256, GSMEM_BYTES>>>(
        p_patch, pw_conv, nullptr, nullptr, p_conv, D_, D_);
    embed_ln_kernel<<<LNB, 256>>>(cls_emb, pos_emb, ln_pre_w, ln_pre_b);

    for (int l = 0; l < L_; l++) {
        ln_kernel<<<LNB, 256>>>(p_x, p_ln, ln1_w + l * D_, ln1_b + l * D_);
        gemm_tc<0, true><<<dim3(MT, 3 * D_ / 128), 256, GSMEM_BYTES>>>(
            p_ln, pw_qkv + (size_t)l * 3 * D_ * D_, qkv_b + (size_t)l * 3 * D_,
            nullptr, p_qkv, 3 * D_, D_);
        attn3_kernel<<<dim3((SEQ_ + TQA - 1) / TQA, B_ * H_), 128, ASMEM_BYTES>>>();
        gemm64<1, false><<<dim3(MT64, D_ / 128), 256, GSMEM64>>>(
            p_att, pw_out + (size_t)l * D_ * D_, out_b + (size_t)l * D_,
            p_x, p_x, D_, D_);
        ln_kernel<<<LNB, 256>>>(p_x, p_ln, ln2_w + l * D_, ln2_b + l * D_);
        gemm_tc<2, true><<<dim3(MT, FF_ / 128), 256, GSMEM_BYTES>>>(
            p_ln, pw_fc + (size_t)l * FF_ * D_, fc_b + (size_t)l * FF_,
            nullptr, p_ff, FF_, D_);
        gemm64<1, false><<<dim3(MT64, D_ / 128), 256, GSMEM64>>>(
            p_ff, pw_pr + (size_t)l * D_ * FF_, pr_b + (size_t)l * D_,
            p_x, p_x, D_, FF_);
    }
    head_kernel<<<B_, 256>>>(ln_post_w, ln_post_b, proj, out);
}